// round 3
// baseline (speedup 1.0000x reference)
#include <cuda_runtime.h>
#include <math.h>

// ---------------- problem constants ----------------
#define D    768
#define DH   3072
#define BB   8
#define TT   8
#define NT   197            // tokens per frame (cls + 196)
#define BT   64             // B*T
#define NHD  12             // heads
#define HD   64             // head dim
#define ST   1569           // T*H*W + 1
#define MXT  (BT*NT)        // 12608 rows in frame-token space
#define MY   (BB*ST)        // 12552 rows in original token space
#define YSZ  (MY*D)         // 9,639,936
#define LMSZ (BT*NT*NT)     // 2,483,776

// ---------------- scratch (device globals: allocation-free) ----------------
__device__ float g_xt [MXT*D];
__device__ float g_qm [MXT*D];
__device__ float g_km [MXT*D];
__device__ float g_xn [MXT*D];        // LN1 out, later LN2 out
__device__ float g_qkv[MXT*3*D];
__device__ float g_o  [MXT*D];
__device__ float g_op [MXT*D];
__device__ float g_h  [MY*DH];

// ---------------- helpers ----------------
__device__ __forceinline__ float tf32r(float x) {
    unsigned r;
    asm("cvt.rna.tf32.f32 %0, %1;" : "=r"(r) : "f"(x));
    return __uint_as_float(r);
}

__device__ __forceinline__ void mma8(float* c, const unsigned* a, const unsigned* b) {
    asm volatile(
        "mma.sync.aligned.m16n8k8.row.col.f32.tf32.tf32.f32 "
        "{%0,%1,%2,%3}, {%4,%5,%6,%7}, {%8,%9}, {%0,%1,%2,%3};"
        : "+f"(c[0]), "+f"(c[1]), "+f"(c[2]), "+f"(c[3])
        : "r"(a[0]), "r"(a[1]), "r"(a[2]), "r"(a[3]), "r"(b[0]), "r"(b[1]));
}

// ---------------- fused gather + LayerNorm1: x -> xt, xn ----------------
__global__ void gather_ln(const float* __restrict__ x, const float* __restrict__ g,
                          const float* __restrict__ be,
                          float* __restrict__ xt, float* __restrict__ xn) {
    int row = blockIdx.x;         // frame-token row (bt*NT + n)
    int tid = threadIdx.x;
    int n  = row % NT;
    int bt = row / NT;
    int b = bt / TT, t = bt % TT;
    int src = (n == 0) ? (b * ST) : (b * ST + 1 + (n - 1) * TT + t);
    const float* xr = x + (long)src * D;
    float v0 = xr[tid], v1 = xr[tid + 256], v2 = xr[tid + 512];
    float* xtr = xt + (long)row * D;
    xtr[tid] = v0; xtr[tid + 256] = v1; xtr[tid + 512] = v2;

    __shared__ float red[256];
    red[tid] = v0 + v1 + v2;
    __syncthreads();
    for (int o = 128; o > 0; o >>= 1) { if (tid < o) red[tid] += red[tid + o]; __syncthreads(); }
    float mean = red[0] * (1.0f / D);
    __syncthreads();
    float d0 = v0 - mean, d1 = v1 - mean, d2 = v2 - mean;
    red[tid] = d0*d0 + d1*d1 + d2*d2;
    __syncthreads();
    for (int o = 128; o > 0; o >>= 1) { if (tid < o) red[tid] += red[tid + o]; __syncthreads(); }
    float rs = rsqrtf(red[0] * (1.0f / D) + 1e-5f);
    float* yr = xn + (long)row * D;
    yr[tid]       = d0 * rs * g[tid]       + be[tid];
    yr[tid + 256] = d1 * rs * g[tid + 256] + be[tid + 256];
    yr[tid + 512] = d2 * rs * g[tid + 512] + be[tid + 512];
}

// ---------------- universal tf32 tensor-core GEMM (double-buffered) ----------------
// C = epi(alpha*A*B^T + bias). A: MxK (lda), B: NxK (ldb) row-major.
// Batch via blockIdx.z enabled when sC != 0. ep: 0=+bias, 1=+bias,gelu, 2=+bias,+Res
__global__ __launch_bounds__(256, 2) void gemm_tf32(
    const float* __restrict__ A, const float* __restrict__ B,
    const float* __restrict__ bias, const float* __restrict__ Res,
    float* __restrict__ C, int M, int N, int K,
    int lda, int ldb, int ldc,
    int inner, int sAi, int sBi, long long sAo, long long sBo, long long sC,
    float alpha, int ep)
{
    __shared__ float As[2][128][20];
    __shared__ float Bs[2][128][20];

    int tid  = threadIdx.x;
    int warp = tid >> 5, lane = tid & 31;
    int g = lane >> 2, tig = lane & 3;
    int wm = warp >> 2;     // 0..1 : 64 rows
    int wn = warp & 3;      // 0..3 : 32 cols
    int m0 = blockIdx.y * 128, n0 = blockIdx.x * 128;

    const float* Ab = A;
    const float* Bb = B;
    float* Cb = C;
    if (sC) {
        int z = blockIdx.z;
        int zo = z / inner, zi = z % inner;
        Ab += (long long)zo * sAo + (long long)zi * sAi;
        Bb += (long long)zo * sBo + (long long)zi * sBi;
        Cb += (long long)z * sC;
    }

    int ldrow = tid >> 1;          // 0..127
    int ldcol = (tid & 1) * 8;     // 0 or 8
    bool aok = (m0 + ldrow) < M;
    bool bok = (n0 + ldrow) < N;
    const float* Ap = Ab + (long long)(m0 + ldrow) * lda + ldcol;
    const float* Bp = Bb + (long long)(n0 + ldrow) * ldb + ldcol;

    const float4 f4z = make_float4(0.f, 0.f, 0.f, 0.f);
    float4 ar0 = aok ? *(const float4*)(Ap)     : f4z;
    float4 ar1 = aok ? *(const float4*)(Ap + 4) : f4z;
    float4 br0 = bok ? *(const float4*)(Bp)     : f4z;
    float4 br1 = bok ? *(const float4*)(Bp + 4) : f4z;

    float acc[4][4][4];
    #pragma unroll
    for (int mt = 0; mt < 4; mt++)
        #pragma unroll
        for (int nt = 0; nt < 4; nt++)
            #pragma unroll
            for (int i = 0; i < 4; i++) acc[mt][nt][i] = 0.f;

#define STAGE(bf) do { \
        float4 t; \
        t = ar0; t.x=tf32r(t.x); t.y=tf32r(t.y); t.z=tf32r(t.z); t.w=tf32r(t.w); \
        *(float4*)&As[bf][ldrow][ldcol] = t; \
        t = ar1; t.x=tf32r(t.x); t.y=tf32r(t.y); t.z=tf32r(t.z); t.w=tf32r(t.w); \
        *(float4*)&As[bf][ldrow][ldcol + 4] = t; \
        t = br0; t.x=tf32r(t.x); t.y=tf32r(t.y); t.z=tf32r(t.z); t.w=tf32r(t.w); \
        *(float4*)&Bs[bf][ldrow][ldcol] = t; \
        t = br1; t.x=tf32r(t.x); t.y=tf32r(t.y); t.z=tf32r(t.z); t.w=tf32r(t.w); \
        *(float4*)&Bs[bf][ldrow][ldcol + 4] = t; \
    } while (0)

    int nkt = K >> 4;
    STAGE(0);
    __syncthreads();

    for (int kt = 0; kt < nkt; kt++) {
        int cur = kt & 1;
        bool has = (kt + 1 < nkt);
        if (has) {
            const float* An = Ap + (kt + 1) * 16;
            const float* Bn = Bp + (kt + 1) * 16;
            ar0 = aok ? *(const float4*)(An)     : f4z;
            ar1 = aok ? *(const float4*)(An + 4) : f4z;
            br0 = bok ? *(const float4*)(Bn)     : f4z;
            br1 = bok ? *(const float4*)(Bn + 4) : f4z;
        }
        #pragma unroll
        for (int ks = 0; ks < 2; ks++) {
            int kk = ks * 8;
            unsigned a[4][4], b[4][2];
            #pragma unroll
            for (int mt = 0; mt < 4; mt++) {
                int r = wm * 64 + mt * 16 + g;
                a[mt][0] = __float_as_uint(As[cur][r][kk + tig]);
                a[mt][1] = __float_as_uint(As[cur][r + 8][kk + tig]);
                a[mt][2] = __float_as_uint(As[cur][r][kk + tig + 4]);
                a[mt][3] = __float_as_uint(As[cur][r + 8][kk + tig + 4]);
            }
            #pragma unroll
            for (int nt = 0; nt < 4; nt++) {
                int r = wn * 32 + nt * 8 + g;
                b[nt][0] = __float_as_uint(Bs[cur][r][kk + tig]);
                b[nt][1] = __float_as_uint(Bs[cur][r][kk + tig + 4]);
            }
            #pragma unroll
            for (int mt = 0; mt < 4; mt++)
                #pragma unroll
                for (int nt = 0; nt < 4; nt++)
                    mma8(acc[mt][nt], a[mt], b[nt]);
        }
        if (has) STAGE(cur ^ 1);
        __syncthreads();
    }
#undef STAGE

    // epilogue
    #pragma unroll
    for (int mt = 0; mt < 4; mt++) {
        int r0 = m0 + wm * 64 + mt * 16 + g;
        #pragma unroll
        for (int nt = 0; nt < 4; nt++) {
            int c0 = n0 + wn * 32 + nt * 8 + tig * 2;
            #pragma unroll
            for (int i = 0; i < 2; i++) {
                int rr = r0 + i * 8;
                if (rr >= M) continue;
                #pragma unroll
                for (int j = 0; j < 2; j++) {
                    int cc = c0 + j;
                    if (cc >= N) continue;
                    float v = acc[mt][nt][i * 2 + j] * alpha;
                    if (bias) v += bias[cc];
                    if (ep == 1) v = 0.5f * v * (1.0f + erff(v * 0.7071067811865476f));
                    else if (ep == 2) v += Res[(long long)rr * ldc + cc];
                    Cb[(long long)rr * ldc + cc] = v;
                }
            }
        }
    }
}

// ---------------- sigmoid over lm logits (with forced [0,0]=100) ----------------
__global__ void sigmoid_lm(float* __restrict__ lm, int total) {
    int idx = blockIdx.x * blockDim.x + threadIdx.x;
    if (idx >= total) return;
    int r = idx % (NT * NT);
    float v = (r == 0) ? 100.0f : lm[idx];
    lm[idx] = 1.0f / (1.0f + expf(-v));
}

// ---------------- fused attention: QK^T (tf32) -> softmax*gate -> AV (tf32) ----------------
// grid (4 q-tiles, NHD, BT), 256 threads. All of K/V for one (bt,h) in smem.
#define SK 68     // stride for Qs/Ks
#define SP 204    // stride for Ps/Vt
#define SM_Q  0
#define SM_K  (SM_Q + 64*SK)            // 4352
#define SM_P  (SM_K + 200*SK)           // 17952
#define SM_V  (SM_P + 64*SP)            // 31008
#define SM_TOT ((SM_V + 64*SP)*4)       // 176256 bytes

__global__ __launch_bounds__(256, 1) void fused_attn(
    const float* __restrict__ qkv, const float* __restrict__ lm, float* __restrict__ o)
{
    extern __shared__ float sm[];
    float* Qs = sm + SM_Q;
    float* Ks = sm + SM_K;
    float* Ps = sm + SM_P;
    float* Vt = sm + SM_V;

    int tid = threadIdx.x;
    int w = tid >> 5, lane = tid & 31;
    int g = lane >> 2, tig = lane & 3;
    int qi = blockIdx.x, h = blockIdx.y, bt = blockIdx.z;
    int q0 = qi * 64;
    const float* base = qkv + (long)bt * NT * 3 * D + h * HD;

    // ---- load Q tile (tf32) ----
    {
        int r = tid >> 2;                 // 0..63
        int c = (tid & 3) * 16;           // 0,16,32,48
        int q = q0 + r;
        if (q < NT) {
            const float* p = base + (long)q * 3 * D + c;
            #pragma unroll
            for (int j = 0; j < 4; j++) {
                float4 v = *(const float4*)(p + j * 4);
                Qs[r*SK + c + j*4 + 0] = tf32r(v.x);
                Qs[r*SK + c + j*4 + 1] = tf32r(v.y);
                Qs[r*SK + c + j*4 + 2] = tf32r(v.z);
                Qs[r*SK + c + j*4 + 3] = tf32r(v.w);
            }
        } else {
            #pragma unroll
            for (int j = 0; j < 16; j++) Qs[r*SK + c + j] = 0.f;
        }
    }
    // ---- load K (all 197 keys, tf32), zero pad rows 197..199 ----
    {
        int c = (tid & 3) * 16;
        for (int r = tid >> 2; r < NT; r += 64) {
            const float* p = base + (long)r * 3 * D + D + c;
            #pragma unroll
            for (int j = 0; j < 4; j++) {
                float4 v = *(const float4*)(p + j * 4);
                Ks[r*SK + c + j*4 + 0] = tf32r(v.x);
                Ks[r*SK + c + j*4 + 1] = tf32r(v.y);
                Ks[r*SK + c + j*4 + 2] = tf32r(v.z);
                Ks[r*SK + c + j*4 + 3] = tf32r(v.w);
            }
        }
        for (int i = tid; i < 3 * 64; i += 256)
            Ks[(197 + i / 64) * SK + (i % 64)] = 0.f;
    }
    // ---- load V transposed (Vt[n][m]), zero pad cols 197..203 ----
    {
        int c4 = (tid & 15) * 4;          // head-dim col
        for (int m = tid >> 4; m < NT; m += 16) {
            float4 v = *(const float4*)(base + (long)m * 3 * D + 2 * D + c4);
            Vt[(c4 + 0) * SP + m] = tf32r(v.x);
            Vt[(c4 + 1) * SP + m] = tf32r(v.y);
            Vt[(c4 + 2) * SP + m] = tf32r(v.z);
            Vt[(c4 + 3) * SP + m] = tf32r(v.w);
        }
        for (int i = tid; i < 64 * 7; i += 256)
            Vt[(i / 7) * SP + 197 + (i % 7)] = 0.f;
    }
    __syncthreads();

    // ---- S = Q @ K^T  (raw scores into Ps) ----
    {
        int wm = w & 3;           // m-tile (16 rows)
        int wn = w >> 2;          // n-half
        int nt0 = wn ? 13 : 0, nt1 = wn ? 25 : 13;
        for (int nt = nt0; nt < nt1; nt++) {
            float c[4] = {0.f, 0.f, 0.f, 0.f};
            #pragma unroll
            for (int kk = 0; kk < 64; kk += 8) {
                unsigned a[4], b[2];
                int ra = wm * 16 + g;
                a[0] = __float_as_uint(Qs[ra*SK + kk + tig]);
                a[1] = __float_as_uint(Qs[(ra + 8)*SK + kk + tig]);
                a[2] = __float_as_uint(Qs[ra*SK + kk + tig + 4]);
                a[3] = __float_as_uint(Qs[(ra + 8)*SK + kk + tig + 4]);
                int rb = nt * 8 + g;
                b[0] = __float_as_uint(Ks[rb*SK + kk + tig]);
                b[1] = __float_as_uint(Ks[rb*SK + kk + tig + 4]);
                mma8(c, a, b);
            }
            int rm = wm * 16 + g, cn = nt * 8 + tig * 2;
            Ps[rm*SP + cn] = c[0];       Ps[rm*SP + cn + 1] = c[1];
            Ps[(rm+8)*SP + cn] = c[2];   Ps[(rm+8)*SP + cn + 1] = c[3];
        }
    }
    __syncthreads();

    // ---- softmax rows + gate, write tf32 probs back to Ps ----
    {
        for (int rr = 0; rr < 8; rr++) {
            int r = (w << 3) + rr;
            int q = q0 + r;
            if (q < NT) {
                const float* lmr = lm + ((long)bt * NT + q) * NT;
                float mx = -1e30f;
                for (int k = lane; k < NT; k += 32) mx = fmaxf(mx, Ps[r*SP + k]);
                #pragma unroll
                for (int s = 16; s > 0; s >>= 1) mx = fmaxf(mx, __shfl_xor_sync(0xffffffffu, mx, s));
                float sum = 0.f;
                for (int k = lane; k < NT; k += 32) {
                    float e = expf(0.125f * (Ps[r*SP + k] - mx));
                    Ps[r*SP + k] = e;
                    sum += e;
                }
                #pragma unroll
                for (int s = 16; s > 0; s >>= 1) sum += __shfl_xor_sync(0xffffffffu, sum, s);
                float inv = 1.0f / sum;
                for (int k = lane; k < 204; k += 32) {
                    float p = (k < NT) ? tf32r(Ps[r*SP + k] * inv * lmr[k]) : 0.f;
                    Ps[r*SP + k] = p;
                }
            } else {
                for (int k = lane; k < 204; k += 32) Ps[r*SP + k] = 0.f;
            }
        }
    }
    __syncthreads();

    // ---- O = P @ V  (tf32) ----
    {
        int wmA = w >> 1;          // 0..3 (16 rows)
        int wnA = w & 1;           // 0..1 (32 cols)
        float acc[4][4];
        #pragma unroll
        for (int nt = 0; nt < 4; nt++)
            #pragma unroll
            for (int i = 0; i < 4; i++) acc[nt][i] = 0.f;

        for (int kk = 0; kk < 200; kk += 8) {
            unsigned a[4], b[4][2];
            int ra = wmA * 16 + g;
            a[0] = __float_as_uint(Ps[ra*SP + kk + tig]);
            a[1] = __float_as_uint(Ps[(ra + 8)*SP + kk + tig]);
            a[2] = __float_as_uint(Ps[ra*SP + kk + tig + 4]);
            a[3] = __float_as_uint(Ps[(ra + 8)*SP + kk + tig + 4]);
            #pragma unroll
            for (int nt = 0; nt < 4; nt++) {
                int rb = wnA * 32 + nt * 8 + g;
                b[nt][0] = __float_as_uint(Vt[rb*SP + kk + tig]);
                b[nt][1] = __float_as_uint(Vt[rb*SP + kk + tig + 4]);
            }
            #pragma unroll
            for (int nt = 0; nt < 4; nt++) mma8(acc[nt], a[nt ? 4 : 0] ? a : a, b[nt]);
        }

        #pragma unroll
        for (int nt = 0; nt < 4; nt++) {
            int cn = wnA * 32 + nt * 8 + tig * 2;
            #pragma unroll
            for (int i = 0; i < 2; i++) {
                int q = q0 + wmA * 16 + g + i * 8;
                if (q >= NT) continue;
                float* op = o + ((long)bt * NT + q) * D + h * HD + cn;
                op[0] = acc[nt][i * 2];
                op[1] = acc[nt][i * 2 + 1];
            }
        }
    }
}

// ---------------- fused scatter(+residual) + LayerNorm2: y, xn ----------------
__global__ void scatter_ln(const float* __restrict__ x, const float* __restrict__ op,
                           const float* __restrict__ g, const float* __restrict__ be,
                           float* __restrict__ y, float* __restrict__ xn) {
    int row = blockIdx.x;      // 0..MY-1
    int tid = threadIdx.x;
    int p = row % ST;
    int b = row / ST;
    float v[3];
    #pragma unroll
    for (int c = 0; c < 3; c++) {
        int d = tid + c * 256;
        float add;
        if (p == 0) {
            float s = 0.f;
            #pragma unroll
            for (int t = 0; t < TT; t++)
                s += op[((long)((b * TT + t) * NT)) * D + d];
            add = s * (1.0f / TT);
        } else {
            int q = p - 1;
            int hw = q / TT, t = q % TT;
            add = op[((long)((b * TT + t) * NT + 1 + hw)) * D + d];
        }
        v[c] = x[(long)row * D + d] + add;
        y[(long)row * D + d] = v[c];
    }
    __shared__ float red[256];
    red[tid] = v[0] + v[1] + v[2];
    __syncthreads();
    for (int o = 128; o > 0; o >>= 1) { if (tid < o) red[tid] += red[tid + o]; __syncthreads(); }
    float mean = red[0] * (1.0f / D);
    __syncthreads();
    float d0 = v[0] - mean, d1 = v[1] - mean, d2 = v[2] - mean;
    red[tid] = d0*d0 + d1*d1 + d2*d2;
    __syncthreads();
    for (int o = 128; o > 0; o >>= 1) { if (tid < o) red[tid] += red[tid + o]; __syncthreads(); }
    float rs = rsqrtf(red[0] * (1.0f / D) + 1e-5f);
    float* yr = xn + (long)row * D;
    yr[tid]       = d0 * rs * g[tid]       + be[tid];
    yr[tid + 256] = d1 * rs * g[tid + 256] + be[tid + 256];
    yr[tid + 512] = d2 * rs * g[tid + 512] + be[tid + 512];
}

// ---------------- launcher ----------------
extern "C" void kernel_launch(void* const* d_in, const int* in_sizes, int n_in,
                              void* d_out, int out_size) {
    const float* x    = (const float*)d_in[0];
    const float* Wmq  = (const float*)d_in[1];
    const float* bmq  = (const float*)d_in[2];
    const float* Wmk  = (const float*)d_in[3];
    const float* bmk  = (const float*)d_in[4];
    const float* g1   = (const float*)d_in[5];
    const float* be1  = (const float*)d_in[6];
    const float* Wqkv = (const float*)d_in[7];
    const float* Wpr  = (const float*)d_in[8];
    const float* bpr  = (const float*)d_in[9];
    const float* g2   = (const float*)d_in[10];
    const float* be2  = (const float*)d_in[11];
    const float* Wf1  = (const float*)d_in[12];
    const float* bf1  = (const float*)d_in[13];
    const float* Wf2  = (const float*)d_in[14];
    const float* bf2  = (const float*)d_in[15];

    float* out = (float*)d_out;
    float* y   = out;
    float* lm  = out + YSZ;

    float *xt, *qm, *km, *xn, *qkv, *o, *op, *h;
    cudaGetSymbolAddress((void**)&xt,  g_xt);
    cudaGetSymbolAddress((void**)&qm,  g_qm);
    cudaGetSymbolAddress((void**)&km,  g_km);
    cudaGetSymbolAddress((void**)&xn,  g_xn);
    cudaGetSymbolAddress((void**)&qkv, g_qkv);
    cudaGetSymbolAddress((void**)&o,   g_o);
    cudaGetSymbolAddress((void**)&op,  g_op);
    cudaGetSymbolAddress((void**)&h,   g_h);

    static int smem_set = 0;
    if (!smem_set) {
        cudaFuncSetAttribute(fused_attn, cudaFuncAttributeMaxDynamicSharedMemorySize, SM_TOT);
        smem_set = 1;
    }

    int gy  = (MXT + 127) / 128;   // 99
    int gy2 = (MY  + 127) / 128;   // 99

    // 1) gather + LN1
    gather_ln<<<MXT, 256>>>(x, g1, be1, xt, xn);

    // 2) mask projections qm, km
    gemm_tf32<<<dim3(D/128, gy), 256>>>(xt, Wmq, bmq, nullptr, qm, MXT, D, D,
                                        D, D, D, 1,0,0,0,0,0, 1.0f, 0);
    gemm_tf32<<<dim3(D/128, gy), 256>>>(xt, Wmk, bmk, nullptr, km, MXT, D, D,
                                        D, D, D, 1,0,0,0,0,0, 1.0f, 0);

    // 3) lm logits (batched over bt), sigmoid with forced [0,0]=100
    gemm_tf32<<<dim3(2, 2, BT), 256>>>(qm, km, nullptr, nullptr, lm, NT, NT, D,
                                       D, D, NT,
                                       1, 0, 0, (long long)NT*D, (long long)NT*D,
                                       (long long)NT*NT, 1.0f, 0);
    sigmoid_lm<<<(LMSZ + 255) / 256, 256>>>(lm, LMSZ);

    // 4) QKV projection (no bias)
    gemm_tf32<<<dim3((3*D)/128, gy), 256>>>(xn, Wqkv, nullptr, nullptr, qkv, MXT, 3*D, D,
                                            D, D, 3*D, 1,0,0,0,0,0, 1.0f, 0);

    // 5) fused attention (QK^T + softmax*gate + AV)
    fused_attn<<<dim3(4, NHD, BT), 256, SM_TOT>>>(qkv, lm, o);

    // 6) output projection, scatter back (+residual) + LN2
    gemm_tf32<<<dim3(D/128, gy), 256>>>(o, Wpr, bpr, nullptr, op, MXT, D, D,
                                        D, D, D, 1,0,0,0,0,0, 1.0f, 0);
    scatter_ln<<<MY, 256>>>(x, op, g2, be2, y, xn);

    // 7) MLP: fc1(+gelu) -> fc2(+residual into y)
    gemm_tf32<<<dim3(DH/128, gy2), 256>>>(xn, Wf1, bf1, nullptr, h, MY, DH, D,
                                          D, D, DH, 1,0,0,0,0,0, 1.0f, 1);
    gemm_tf32<<<dim3(D/128, gy2), 256>>>(h, Wf2, bf2, y, y, MY, D, DH,
                                         DH, DH, D, 1,0,0,0,0,0, 1.0f, 2);
}

// round 4
// speedup vs baseline: 1.1140x; 1.1140x over previous
#include <cuda_runtime.h>
#include <math.h>

// ---------------- problem constants ----------------
#define D    768
#define DH   3072
#define BB   8
#define TT   8
#define NT   197            // tokens per frame (cls + 196)
#define BT   64             // B*T
#define NHD  12             // heads
#define HD   64             // head dim
#define ST   1569           // T*H*W + 1
#define MXT  (BT*NT)        // 12608 rows in frame-token space
#define MY   (BB*ST)        // 12552 rows in original token space
#define YSZ  (MY*D)         // 9,639,936
#define LMSZ (BT*NT*NT)     // 2,483,776

// ---------------- scratch (device globals: allocation-free) ----------------
__device__ float g_xt [MXT*D];
__device__ float g_qm [MXT*D];
__device__ float g_km [MXT*D];
__device__ float g_xn [MXT*D];        // LN1 out, later LN2 out
__device__ float g_qkv[MXT*3*D];
__device__ float g_o  [MXT*D];
__device__ float g_op [MXT*D];
__device__ float g_h  [MY*DH];

// ---------------- helpers ----------------
__device__ __forceinline__ float tf32r(float x) {
    unsigned r;
    asm("cvt.rna.tf32.f32 %0, %1;" : "=r"(r) : "f"(x));
    return __uint_as_float(r);
}

__device__ __forceinline__ void mma8(float* c, const unsigned* a, const unsigned* b) {
    asm volatile(
        "mma.sync.aligned.m16n8k8.row.col.f32.tf32.tf32.f32 "
        "{%0,%1,%2,%3}, {%4,%5,%6,%7}, {%8,%9}, {%0,%1,%2,%3};"
        : "+f"(c[0]), "+f"(c[1]), "+f"(c[2]), "+f"(c[3])
        : "r"(a[0]), "r"(a[1]), "r"(a[2]), "r"(a[3]), "r"(b[0]), "r"(b[1]));
}

__device__ __forceinline__ void ldsm_x4(unsigned* r, unsigned addr) {
    asm volatile("ldmatrix.sync.aligned.m8n8.x4.shared.b16 {%0,%1,%2,%3}, [%4];"
        : "=r"(r[0]), "=r"(r[1]), "=r"(r[2]), "=r"(r[3]) : "r"(addr));
}

// ---------------- fused gather + LayerNorm1: x -> xt, xn ----------------
__global__ void gather_ln(const float* __restrict__ x, const float* __restrict__ g,
                          const float* __restrict__ be,
                          float* __restrict__ xt, float* __restrict__ xn) {
    int row = blockIdx.x;         // frame-token row (bt*NT + n)
    int tid = threadIdx.x;
    int n  = row % NT;
    int bt = row / NT;
    int b = bt / TT, t = bt % TT;
    int src = (n == 0) ? (b * ST) : (b * ST + 1 + (n - 1) * TT + t);
    const float* xr = x + (long)src * D;
    float v0 = xr[tid], v1 = xr[tid + 256], v2 = xr[tid + 512];
    float* xtr = xt + (long)row * D;
    xtr[tid] = v0; xtr[tid + 256] = v1; xtr[tid + 512] = v2;

    __shared__ float red[256];
    red[tid] = v0 + v1 + v2;
    __syncthreads();
    for (int o = 128; o > 0; o >>= 1) { if (tid < o) red[tid] += red[tid + o]; __syncthreads(); }
    float mean = red[0] * (1.0f / D);
    __syncthreads();
    float d0 = v0 - mean, d1 = v1 - mean, d2 = v2 - mean;
    red[tid] = d0*d0 + d1*d1 + d2*d2;
    __syncthreads();
    for (int o = 128; o > 0; o >>= 1) { if (tid < o) red[tid] += red[tid + o]; __syncthreads(); }
    float rs = rsqrtf(red[0] * (1.0f / D) + 1e-5f);
    float* yr = xn + (long)row * D;
    yr[tid]       = d0 * rs * g[tid]       + be[tid];
    yr[tid + 256] = d1 * rs * g[tid + 256] + be[tid + 256];
    yr[tid + 512] = d2 * rs * g[tid + 512] + be[tid + 512];
}

// ---------------- universal tf32 tensor-core GEMM (double-buffered + ldmatrix) ----------------
// C = epi(alpha*A*B^T + bias). A: MxK (lda), B: NxK (ldb) row-major.
// Batch via blockIdx.z enabled when sC != 0. ep: 0=+bias, 1=+bias,gelu, 2=+bias,+Res
__global__ __launch_bounds__(256, 2) void gemm_tf32(
    const float* __restrict__ A, const float* __restrict__ B,
    const float* __restrict__ bias, const float* __restrict__ Res,
    float* __restrict__ C, int M, int N, int K,
    int lda, int ldb, int ldc,
    int inner, int sAi, int sBi, long long sAo, long long sBo, long long sC,
    float alpha, int ep)
{
    __shared__ __align__(16) float As[2][128][20];   // stride 20: LDSM conflict-free
    __shared__ __align__(16) float Bs[2][128][20];

    int tid  = threadIdx.x;
    int warp = tid >> 5, lane = tid & 31;
    int g = lane >> 2, tig = lane & 3;
    int wm = warp >> 2;     // 0..1 : 64 rows
    int wn = warp & 3;      // 0..3 : 32 cols
    int m0 = blockIdx.y * 128, n0 = blockIdx.x * 128;

    const float* Ab = A;
    const float* Bb = B;
    float* Cb = C;
    if (sC) {
        int z = blockIdx.z;
        int zo = z / inner, zi = z % inner;
        Ab += (long long)zo * sAo + (long long)zi * sAi;
        Bb += (long long)zo * sBo + (long long)zi * sBi;
        Cb += (long long)z * sC;
    }

    int ldrow = tid >> 1;          // 0..127
    int ldcol = (tid & 1) * 8;     // 0 or 8
    bool aok = (m0 + ldrow) < M;
    bool bok = (n0 + ldrow) < N;
    const float* Ap = Ab + (long long)(m0 + ldrow) * lda + ldcol;
    const float* Bp = Bb + (long long)(n0 + ldrow) * ldb + ldcol;

    // ldmatrix per-thread source addresses (A: 16-row m-tiles; B: paired 8-n blocks)
    unsigned aSm = (unsigned)__cvta_generic_to_shared(&As[0][0][0]);
    unsigned bSm = (unsigned)__cvta_generic_to_shared(&Bs[0][0][0]);
    int arow = lane & 15;
    int acol = (lane >> 4) * 4;                         // 0 or 4
    int brow = (lane & 7) + ((lane & 16) >> 1);          // 0..7 / +8
    int bcol = ((lane >> 3) & 1) * 4;                    // 0 or 4
    unsigned aAddr = aSm + ((wm * 64 + arow) * 20 + acol) * 4;
    unsigned bAddr = bSm + ((wn * 32 + brow) * 20 + bcol) * 4;
    const unsigned BUF = 128 * 20 * 4;                   // 10240 bytes

    const float4 f4z = make_float4(0.f, 0.f, 0.f, 0.f);
    float4 ar0 = aok ? *(const float4*)(Ap)     : f4z;
    float4 ar1 = aok ? *(const float4*)(Ap + 4) : f4z;
    float4 br0 = bok ? *(const float4*)(Bp)     : f4z;
    float4 br1 = bok ? *(const float4*)(Bp + 4) : f4z;

    float acc[4][4][4];
    #pragma unroll
    for (int mt = 0; mt < 4; mt++)
        #pragma unroll
        for (int nt = 0; nt < 4; nt++)
            #pragma unroll
            for (int i = 0; i < 4; i++) acc[mt][nt][i] = 0.f;

#define STAGE(bf) do { \
        float4 t; \
        t = ar0; t.x=tf32r(t.x); t.y=tf32r(t.y); t.z=tf32r(t.z); t.w=tf32r(t.w); \
        *(float4*)&As[bf][ldrow][ldcol] = t; \
        t = ar1; t.x=tf32r(t.x); t.y=tf32r(t.y); t.z=tf32r(t.z); t.w=tf32r(t.w); \
        *(float4*)&As[bf][ldrow][ldcol + 4] = t; \
        t = br0; t.x=tf32r(t.x); t.y=tf32r(t.y); t.z=tf32r(t.z); t.w=tf32r(t.w); \
        *(float4*)&Bs[bf][ldrow][ldcol] = t; \
        t = br1; t.x=tf32r(t.x); t.y=tf32r(t.y); t.z=tf32r(t.z); t.w=tf32r(t.w); \
        *(float4*)&Bs[bf][ldrow][ldcol + 4] = t; \
    } while (0)

    int nkt = K >> 4;
    STAGE(0);
    __syncthreads();

    for (int kt = 0; kt < nkt; kt++) {
        int cur = kt & 1;
        bool has = (kt + 1 < nkt);
        if (has) {
            const float* An = Ap + (kt + 1) * 16;
            const float* Bn = Bp + (kt + 1) * 16;
            ar0 = aok ? *(const float4*)(An)     : f4z;
            ar1 = aok ? *(const float4*)(An + 4) : f4z;
            br0 = bok ? *(const float4*)(Bn)     : f4z;
            br1 = bok ? *(const float4*)(Bn + 4) : f4z;
        }
        unsigned aB = aAddr + cur * BUF;
        unsigned bB = bAddr + cur * BUF;
        #pragma unroll
        for (int ks = 0; ks < 2; ks++) {
            unsigned kko = ks * 32;   // 8 floats = 32 bytes
            unsigned a[4][4], b[2][4];
            #pragma unroll
            for (int mt = 0; mt < 4; mt++)
                ldsm_x4(a[mt], aB + mt * (16 * 20 * 4) + kko);
            #pragma unroll
            for (int p = 0; p < 2; p++)
                ldsm_x4(b[p], bB + p * (16 * 20 * 4) + kko);
            #pragma unroll
            for (int mt = 0; mt < 4; mt++)
                #pragma unroll
                for (int nt = 0; nt < 4; nt++) {
                    unsigned bb[2] = { b[nt >> 1][(nt & 1) * 2], b[nt >> 1][(nt & 1) * 2 + 1] };
                    mma8(acc[mt][nt], a[mt], bb);
                }
        }
        if (has) STAGE(cur ^ 1);
        __syncthreads();
    }
#undef STAGE

    // epilogue
    #pragma unroll
    for (int mt = 0; mt < 4; mt++) {
        int r0 = m0 + wm * 64 + mt * 16 + g;
        #pragma unroll
        for (int nt = 0; nt < 4; nt++) {
            int c0 = n0 + wn * 32 + nt * 8 + tig * 2;
            #pragma unroll
            for (int i = 0; i < 2; i++) {
                int rr = r0 + i * 8;
                if (rr >= M) continue;
                #pragma unroll
                for (int j = 0; j < 2; j++) {
                    int cc = c0 + j;
                    if (cc >= N) continue;
                    float v = acc[mt][nt][i * 2 + j] * alpha;
                    if (bias) v += bias[cc];
                    if (ep == 1) v = 0.5f * v * (1.0f + erff(v * 0.7071067811865476f));
                    else if (ep == 2) v += Res[(long long)rr * ldc + cc];
                    Cb[(long long)rr * ldc + cc] = v;
                }
            }
        }
    }
}

// ---------------- sigmoid over lm logits (with forced [0,0]=100) ----------------
__global__ void sigmoid_lm(float* __restrict__ lm, int total) {
    int idx = blockIdx.x * blockDim.x + threadIdx.x;
    if (idx >= total) return;
    int r = idx % (NT * NT);
    float v = (r == 0) ? 100.0f : lm[idx];
    lm[idx] = 1.0f / (1.0f + expf(-v));
}

// ---------------- fused attention: QK^T (tf32) -> softmax*gate -> AV (tf32) ----------------
#define SK 68     // stride for Qs/Ks
#define SP 204    // stride for Ps/Vt
#define SM_Q  0
#define SM_K  (SM_Q + 64*SK)
#define SM_P  (SM_K + 200*SK)
#define SM_V  (SM_P + 64*SP)
#define SM_TOT ((SM_V + 64*SP)*4)

__global__ __launch_bounds__(256, 1) void fused_attn(
    const float* __restrict__ qkv, const float* __restrict__ lm, float* __restrict__ o)
{
    extern __shared__ float sm[];
    float* Qs = sm + SM_Q;
    float* Ks = sm + SM_K;
    float* Ps = sm + SM_P;
    float* Vt = sm + SM_V;

    int tid = threadIdx.x;
    int w = tid >> 5, lane = tid & 31;
    int g = lane >> 2, tig = lane & 3;
    int qi = blockIdx.x, h = blockIdx.y, bt = blockIdx.z;
    int q0 = qi * 64;
    const float* base = qkv + (long)bt * NT * 3 * D + h * HD;

    // ---- load Q tile (tf32) ----
    {
        int r = tid >> 2;
        int c = (tid & 3) * 16;
        int q = q0 + r;
        if (q < NT) {
            const float* p = base + (long)q * 3 * D + c;
            #pragma unroll
            for (int j = 0; j < 4; j++) {
                float4 v = *(const float4*)(p + j * 4);
                Qs[r*SK + c + j*4 + 0] = tf32r(v.x);
                Qs[r*SK + c + j*4 + 1] = tf32r(v.y);
                Qs[r*SK + c + j*4 + 2] = tf32r(v.z);
                Qs[r*SK + c + j*4 + 3] = tf32r(v.w);
            }
        } else {
            #pragma unroll
            for (int j = 0; j < 16; j++) Qs[r*SK + c + j] = 0.f;
        }
    }
    // ---- load K (all 197 keys, tf32), zero pad rows 197..199 ----
    {
        int c = (tid & 3) * 16;
        for (int r = tid >> 2; r < NT; r += 64) {
            const float* p = base + (long)r * 3 * D + D + c;
            #pragma unroll
            for (int j = 0; j < 4; j++) {
                float4 v = *(const float4*)(p + j * 4);
                Ks[r*SK + c + j*4 + 0] = tf32r(v.x);
                Ks[r*SK + c + j*4 + 1] = tf32r(v.y);
                Ks[r*SK + c + j*4 + 2] = tf32r(v.z);
                Ks[r*SK + c + j*4 + 3] = tf32r(v.w);
            }
        }
        for (int i = tid; i < 3 * 64; i += 256)
            Ks[(197 + i / 64) * SK + (i % 64)] = 0.f;
    }
    // ---- load V transposed (Vt[n][m]), zero pad cols 197..203 ----
    {
        int c4 = (tid & 15) * 4;
        for (int m = tid >> 4; m < NT; m += 16) {
            float4 v = *(const float4*)(base + (long)m * 3 * D + 2 * D + c4);
            Vt[(c4 + 0) * SP + m] = tf32r(v.x);
            Vt[(c4 + 1) * SP + m] = tf32r(v.y);
            Vt[(c4 + 2) * SP + m] = tf32r(v.z);
            Vt[(c4 + 3) * SP + m] = tf32r(v.w);
        }
        for (int i = tid; i < 64 * 7; i += 256)
            Vt[(i / 7) * SP + 197 + (i % 7)] = 0.f;
    }
    __syncthreads();

    // ---- S = Q @ K^T ----
    {
        int wm = w & 3;
        int wn = w >> 2;
        int nt0 = wn ? 13 : 0, nt1 = wn ? 25 : 13;
        for (int nt = nt0; nt < nt1; nt++) {
            float c[4] = {0.f, 0.f, 0.f, 0.f};
            #pragma unroll
            for (int kk = 0; kk < 64; kk += 8) {
                unsigned a[4], b[2];
                int ra = wm * 16 + g;
                a[0] = __float_as_uint(Qs[ra*SK + kk + tig]);
                a[1] = __float_as_uint(Qs[(ra + 8)*SK + kk + tig]);
                a[2] = __float_as_uint(Qs[ra*SK + kk + tig + 4]);
                a[3] = __float_as_uint(Qs[(ra + 8)*SK + kk + tig + 4]);
                int rb = nt * 8 + g;
                b[0] = __float_as_uint(Ks[rb*SK + kk + tig]);
                b[1] = __float_as_uint(Ks[rb*SK + kk + tig + 4]);
                mma8(c, a, b);
            }
            int rm = wm * 16 + g, cn = nt * 8 + tig * 2;
            Ps[rm*SP + cn] = c[0];       Ps[rm*SP + cn + 1] = c[1];
            Ps[(rm+8)*SP + cn] = c[2];   Ps[(rm+8)*SP + cn + 1] = c[3];
        }
    }
    __syncthreads();

    // ---- softmax rows + gate ----
    {
        for (int rr = 0; rr < 8; rr++) {
            int r = (w << 3) + rr;
            int q = q0 + r;
            if (q < NT) {
                const float* lmr = lm + ((long)bt * NT + q) * NT;
                float mx = -1e30f;
                for (int k = lane; k < NT; k += 32) mx = fmaxf(mx, Ps[r*SP + k]);
                #pragma unroll
                for (int s = 16; s > 0; s >>= 1) mx = fmaxf(mx, __shfl_xor_sync(0xffffffffu, mx, s));
                float sum = 0.f;
                for (int k = lane; k < NT; k += 32) {
                    float e = expf(0.125f * (Ps[r*SP + k] - mx));
                    Ps[r*SP + k] = e;
                    sum += e;
                }
                #pragma unroll
                for (int s = 16; s > 0; s >>= 1) sum += __shfl_xor_sync(0xffffffffu, sum, s);
                float inv = 1.0f / sum;
                for (int k = lane; k < 204; k += 32) {
                    float p = (k < NT) ? tf32r(Ps[r*SP + k] * inv * lmr[k]) : 0.f;
                    Ps[r*SP + k] = p;
                }
            } else {
                for (int k = lane; k < 204; k += 32) Ps[r*SP + k] = 0.f;
            }
        }
    }
    __syncthreads();

    // ---- O = P @ V ----
    {
        int wmA = w >> 1;
        int wnA = w & 1;
        float acc[4][4];
        #pragma unroll
        for (int nt = 0; nt < 4; nt++)
            #pragma unroll
            for (int i = 0; i < 4; i++) acc[nt][i] = 0.f;

        for (int kk = 0; kk < 200; kk += 8) {
            unsigned a[4], b[4][2];
            int ra = wmA * 16 + g;
            a[0] = __float_as_uint(Ps[ra*SP + kk + tig]);
            a[1] = __float_as_uint(Ps[(ra + 8)*SP + kk + tig]);
            a[2] = __float_as_uint(Ps[ra*SP + kk + tig + 4]);
            a[3] = __float_as_uint(Ps[(ra + 8)*SP + kk + tig + 4]);
            #pragma unroll
            for (int nt = 0; nt < 4; nt++) {
                int rb = wnA * 32 + nt * 8 + g;
                b[nt][0] = __float_as_uint(Vt[rb*SP + kk + tig]);
                b[nt][1] = __float_as_uint(Vt[rb*SP + kk + tig + 4]);
            }
            #pragma unroll
            for (int nt = 0; nt < 4; nt++) mma8(acc[nt], a, b[nt]);
        }

        #pragma unroll
        for (int nt = 0; nt < 4; nt++) {
            int cn = wnA * 32 + nt * 8 + tig * 2;
            #pragma unroll
            for (int i = 0; i < 2; i++) {
                int q = q0 + wmA * 16 + g + i * 8;
                if (q >= NT) continue;
                float* op = o + ((long)bt * NT + q) * D + h * HD + cn;
                op[0] = acc[nt][i * 2];
                op[1] = acc[nt][i * 2 + 1];
            }
        }
    }
}

// ---------------- fused scatter(+residual) + LayerNorm2: y, xn ----------------
__global__ void scatter_ln(const float* __restrict__ x, const float* __restrict__ op,
                           const float* __restrict__ g, const float* __restrict__ be,
                           float* __restrict__ y, float* __restrict__ xn) {
    int row = blockIdx.x;
    int tid = threadIdx.x;
    int p = row % ST;
    int b = row / ST;
    float v[3];
    #pragma unroll
    for (int c = 0; c < 3; c++) {
        int d = tid + c * 256;
        float add;
        if (p == 0) {
            float s = 0.f;
            #pragma unroll
            for (int t = 0; t < TT; t++)
                s += op[((long)((b * TT + t) * NT)) * D + d];
            add = s * (1.0f / TT);
        } else {
            int q = p - 1;
            int hw = q / TT, t = q % TT;
            add = op[((long)((b * TT + t) * NT + 1 + hw)) * D + d];
        }
        v[c] = x[(long)row * D + d] + add;
        y[(long)row * D + d] = v[c];
    }
    __shared__ float red[256];
    red[tid] = v[0] + v[1] + v[2];
    __syncthreads();
    for (int o = 128; o > 0; o >>= 1) { if (tid < o) red[tid] += red[tid + o]; __syncthreads(); }
    float mean = red[0] * (1.0f / D);
    __syncthreads();
    float d0 = v[0] - mean, d1 = v[1] - mean, d2 = v[2] - mean;
    red[tid] = d0*d0 + d1*d1 + d2*d2;
    __syncthreads();
    for (int o = 128; o > 0; o >>= 1) { if (tid < o) red[tid] += red[tid + o]; __syncthreads(); }
    float rs = rsqrtf(red[0] * (1.0f / D) + 1e-5f);
    float* yr = xn + (long)row * D;
    yr[tid]       = d0 * rs * g[tid]       + be[tid];
    yr[tid + 256] = d1 * rs * g[tid + 256] + be[tid + 256];
    yr[tid + 512] = d2 * rs * g[tid + 512] + be[tid + 512];
}

// ---------------- launcher ----------------
extern "C" void kernel_launch(void* const* d_in, const int* in_sizes, int n_in,
                              void* d_out, int out_size) {
    const float* x    = (const float*)d_in[0];
    const float* Wmq  = (const float*)d_in[1];
    const float* bmq  = (const float*)d_in[2];
    const float* Wmk  = (const float*)d_in[3];
    const float* bmk  = (const float*)d_in[4];
    const float* g1   = (const float*)d_in[5];
    const float* be1  = (const float*)d_in[6];
    const float* Wqkv = (const float*)d_in[7];
    const float* Wpr  = (const float*)d_in[8];
    const float* bpr  = (const float*)d_in[9];
    const float* g2   = (const float*)d_in[10];
    const float* be2  = (const float*)d_in[11];
    const float* Wf1  = (const float*)d_in[12];
    const float* bf1  = (const float*)d_in[13];
    const float* Wf2  = (const float*)d_in[14];
    const float* bf2  = (const float*)d_in[15];

    float* out = (float*)d_out;
    float* y   = out;
    float* lm  = out + YSZ;

    float *xt, *qm, *km, *xn, *qkv, *o, *op, *h;
    cudaGetSymbolAddress((void**)&xt,  g_xt);
    cudaGetSymbolAddress((void**)&qm,  g_qm);
    cudaGetSymbolAddress((void**)&km,  g_km);
    cudaGetSymbolAddress((void**)&xn,  g_xn);
    cudaGetSymbolAddress((void**)&qkv, g_qkv);
    cudaGetSymbolAddress((void**)&o,   g_o);
    cudaGetSymbolAddress((void**)&op,  g_op);
    cudaGetSymbolAddress((void**)&h,   g_h);

    static int smem_set = 0;
    if (!smem_set) {
        cudaFuncSetAttribute(fused_attn, cudaFuncAttributeMaxDynamicSharedMemorySize, SM_TOT);
        smem_set = 1;
    }

    int gy  = (MXT + 127) / 128;   // 99
    int gy2 = (MY  + 127) / 128;   // 99

    // 1) gather + LN1
    gather_ln<<<MXT, 256>>>(x, g1, be1, xt, xn);

    // 2) mask projections qm, km
    gemm_tf32<<<dim3(D/128, gy), 256>>>(xt, Wmq, bmq, nullptr, qm, MXT, D, D,
                                        D, D, D, 1,0,0,0,0,0, 1.0f, 0);
    gemm_tf32<<<dim3(D/128, gy), 256>>>(xt, Wmk, bmk, nullptr, km, MXT, D, D,
                                        D, D, D, 1,0,0,0,0,0, 1.0f, 0);

    // 3) lm logits (batched over bt), sigmoid with forced [0,0]=100
    gemm_tf32<<<dim3(2, 2, BT), 256>>>(qm, km, nullptr, nullptr, lm, NT, NT, D,
                                       D, D, NT,
                                       1, 0, 0, (long long)NT*D, (long long)NT*D,
                                       (long long)NT*NT, 1.0f, 0);
    sigmoid_lm<<<(LMSZ + 255) / 256, 256>>>(lm, LMSZ);

    // 4) QKV projection (no bias)
    gemm_tf32<<<dim3((3*D)/128, gy), 256>>>(xn, Wqkv, nullptr, nullptr, qkv, MXT, 3*D, D,
                                            D, D, 3*D, 1,0,0,0,0,0, 1.0f, 0);

    // 5) fused attention (QK^T + softmax*gate + AV)
    fused_attn<<<dim3(4, NHD, BT), 256, SM_TOT>>>(qkv, lm, o);

    // 6) output projection, scatter back (+residual) + LN2
    gemm_tf32<<<dim3(D/128, gy), 256>>>(o, Wpr, bpr, nullptr, op, MXT, D, D,
                                        D, D, D, 1,0,0,0,0,0, 1.0f, 0);
    scatter_ln<<<MY, 256>>>(x, op, g2, be2, y, xn);

    // 7) MLP: fc1(+gelu) -> fc2(+residual into y)
    gemm_tf32<<<dim3(DH/128, gy2), 256>>>(xn, Wf1, bf1, nullptr, h, MY, DH, D,
                                          D, D, DH, 1,0,0,0,0,0, 1.0f, 1);
    gemm_tf32<<<dim3(D/128, gy2), 256>>>(h, Wf2, bf2, y, y, MY, D, DH,
                                         DH, DH, D, 1,0,0,0,0,0, 1.0f, 2);
}

// round 5
// speedup vs baseline: 1.2368x; 1.1102x over previous
#include <cuda_runtime.h>
#include <math.h>

// ---------------- problem constants ----------------
#define D    768
#define DH   3072
#define BB   8
#define TT   8
#define NT   197            // tokens per frame (cls + 196)
#define BT   64             // B*T
#define NHD  12             // heads
#define HD   64             // head dim
#define ST   1569           // T*H*W + 1
#define MXT  (BT*NT)        // 12608 rows in frame-token space
#define MY   (BB*ST)        // 12552 rows in original token space
#define YSZ  (MY*D)         // 9,639,936
#define LMSZ (BT*NT*NT)     // 2,483,776

#define GS   4              // cp.async pipeline stages
#define SMEM_G (GS*2*128*20*4)   // 81920 bytes

// ---------------- scratch (device globals: allocation-free) ----------------
__device__ float g_xt [MXT*D];
__device__ float g_qmk[MXT*2*D];      // [qm | km] fused
__device__ float g_wqk[2*D*D];        // [Wmq ; Wmk]
__device__ float g_bqk[2*D];
__device__ float g_xn [MXT*D];        // LN1 out, later LN2 out
__device__ float g_qkv[MXT*3*D];
__device__ float g_o  [MXT*D];
__device__ float g_op [MXT*D];
__device__ float g_h  [MY*DH];

// ---------------- helpers ----------------
__device__ __forceinline__ float tf32r(float x) {
    unsigned r;
    asm("cvt.rna.tf32.f32 %0, %1;" : "=r"(r) : "f"(x));
    return __uint_as_float(r);
}

__device__ __forceinline__ void mma8(float* c, const unsigned* a, const unsigned* b) {
    asm volatile(
        "mma.sync.aligned.m16n8k8.row.col.f32.tf32.tf32.f32 "
        "{%0,%1,%2,%3}, {%4,%5,%6,%7}, {%8,%9}, {%0,%1,%2,%3};"
        : "+f"(c[0]), "+f"(c[1]), "+f"(c[2]), "+f"(c[3])
        : "r"(a[0]), "r"(a[1]), "r"(a[2]), "r"(a[3]), "r"(b[0]), "r"(b[1]));
}

__device__ __forceinline__ void ldsm_x4(unsigned* r, unsigned addr) {
    asm volatile("ldmatrix.sync.aligned.m8n8.x4.shared.b16 {%0,%1,%2,%3}, [%4];"
        : "=r"(r[0]), "=r"(r[1]), "=r"(r[2]), "=r"(r[3]) : "r"(addr));
}

__device__ __forceinline__ void cpa16(unsigned dst, const float* src, bool p) {
    asm volatile("cp.async.cg.shared.global [%0], [%1], 16, %2;"
        :: "r"(dst), "l"(src), "r"(p ? 16 : 0));
}
#define CP_COMMIT asm volatile("cp.async.commit_group;")
template<int N> __device__ __forceinline__ void cp_wait() {
    asm volatile("cp.async.wait_group %0;" :: "n"(N));
}

// ---------------- concat Wmq/Wmk -> wqk, bmq/bmk -> bqk ----------------
__global__ void concat_qk(const float* __restrict__ Wmq, const float* __restrict__ Wmk,
                          const float* __restrict__ bmq, const float* __restrict__ bmk,
                          float* __restrict__ W, float* __restrict__ b2) {
    int i = blockIdx.x * blockDim.x + threadIdx.x;
    const int half = D * D;
    if (i < half) W[i] = Wmq[i];
    else if (i < 2 * half) W[i] = Wmk[i - half];
    if (i < D) b2[i] = bmq[i];
    else if (i < 2 * D) b2[i] = bmk[i - D];
}

// ---------------- fused gather + LayerNorm1: x -> xt, xn ----------------
__global__ void gather_ln(const float* __restrict__ x, const float* __restrict__ g,
                          const float* __restrict__ be,
                          float* __restrict__ xt, float* __restrict__ xn) {
    int row = blockIdx.x;
    int tid = threadIdx.x;
    int n  = row % NT;
    int bt = row / NT;
    int b = bt / TT, t = bt % TT;
    int src = (n == 0) ? (b * ST) : (b * ST + 1 + (n - 1) * TT + t);
    const float* xr = x + (long)src * D;
    float v0 = xr[tid], v1 = xr[tid + 256], v2 = xr[tid + 512];
    float* xtr = xt + (long)row * D;
    xtr[tid] = v0; xtr[tid + 256] = v1; xtr[tid + 512] = v2;

    __shared__ float red[256];
    red[tid] = v0 + v1 + v2;
    __syncthreads();
    for (int o = 128; o > 0; o >>= 1) { if (tid < o) red[tid] += red[tid + o]; __syncthreads(); }
    float mean = red[0] * (1.0f / D);
    __syncthreads();
    float d0 = v0 - mean, d1 = v1 - mean, d2 = v2 - mean;
    red[tid] = d0*d0 + d1*d1 + d2*d2;
    __syncthreads();
    for (int o = 128; o > 0; o >>= 1) { if (tid < o) red[tid] += red[tid + o]; __syncthreads(); }
    float rs = rsqrtf(red[0] * (1.0f / D) + 1e-5f);
    float* yr = xn + (long)row * D;
    yr[tid]       = d0 * rs * g[tid]       + be[tid];
    yr[tid + 256] = d1 * rs * g[tid + 256] + be[tid + 256];
    yr[tid + 512] = d2 * rs * g[tid + 512] + be[tid + 512];
}

// ---------------- universal tf32 GEMM: cp.async 4-stage + ldmatrix ----------------
// C = epi(alpha*A*B^T + bias). A: MxK (lda), B: NxK (ldb) row-major.
// Batch via blockIdx.z when sC != 0. ep: 0=+bias, 1=+bias,gelu, 2=+bias,+Res
__global__ __launch_bounds__(256, 2) void gemm_tf32(
    const float* __restrict__ A, const float* __restrict__ B,
    const float* __restrict__ bias, const float* __restrict__ Res,
    float* __restrict__ C, int M, int N, int K,
    int lda, int ldb, int ldc,
    int inner, int sAi, int sBi, long long sAo, long long sBo, long long sC,
    float alpha, int ep)
{
    extern __shared__ __align__(16) float dyn[];   // A stages then B stages

    int tid  = threadIdx.x;
    int warp = tid >> 5, lane = tid & 31;
    int g = lane >> 2, tig = lane & 3;
    int wm = warp >> 2;     // 0..1 : 64 rows
    int wn = warp & 3;      // 0..3 : 32 cols
    int m0 = blockIdx.y * 128, n0 = blockIdx.x * 128;

    const float* Ab = A;
    const float* Bb = B;
    float* Cb = C;
    if (sC) {
        int z = blockIdx.z;
        int zo = z / inner, zi = z % inner;
        Ab += (long long)zo * sAo + (long long)zi * sAi;
        Bb += (long long)zo * sBo + (long long)zi * sBi;
        Cb += (long long)z * sC;
    }

    int ldrow = tid >> 1;          // 0..127
    int ldcol = (tid & 1) * 8;     // 0 or 8
    bool aok = (m0 + ldrow) < M;
    bool bok = (n0 + ldrow) < N;
    const float* Ap = Ab + (long long)(m0 + ldrow) * lda + ldcol;
    const float* Bp = Bb + (long long)(n0 + ldrow) * ldb + ldcol;

    unsigned smB = (unsigned)__cvta_generic_to_shared(dyn);
    const unsigned STG = 128 * 20 * 4;            // 10240 bytes per stage
    unsigned aSt = smB + (ldrow * 20 + ldcol) * 4;
    unsigned bSt = smB + GS * STG + (ldrow * 20 + ldcol) * 4;

    // ldmatrix per-thread addresses
    int arow = lane & 15;
    int acol = (lane >> 4) * 4;
    int brow = (lane & 7) + ((lane & 16) >> 1);
    int bcol = ((lane >> 3) & 1) * 4;
    unsigned aAddr = smB + ((wm * 64 + arow) * 20 + acol) * 4;
    unsigned bAddr = smB + GS * STG + ((wn * 32 + brow) * 20 + bcol) * 4;

    float acc[4][4][4];
    #pragma unroll
    for (int mt = 0; mt < 4; mt++)
        #pragma unroll
        for (int nt = 0; nt < 4; nt++)
            #pragma unroll
            for (int i = 0; i < 4; i++) acc[mt][nt][i] = 0.f;

    int nkt = K >> 4;

    // prologue: prefetch GS-1 tiles
    #pragma unroll
    for (int s = 0; s < GS - 1; s++) {
        bool has = s < nkt;
        cpa16(aSt + s * STG,      Ap + s * 16,     aok && has);
        cpa16(aSt + s * STG + 16, Ap + s * 16 + 4, aok && has);
        cpa16(bSt + s * STG,      Bp + s * 16,     bok && has);
        cpa16(bSt + s * STG + 16, Bp + s * 16 + 4, bok && has);
        CP_COMMIT;
    }

#define TFC(x) x = __float_as_uint(tf32r(__uint_as_float(x)))
#define LOADFRAG(aB, bB, kko) do { \
        ldsm_x4(fa[0], (aB) + 0 * 1280 + (kko)); \
        ldsm_x4(fa[1], (aB) + 1 * 1280 + (kko)); \
        ldsm_x4(fa[2], (aB) + 2 * 1280 + (kko)); \
        ldsm_x4(fa[3], (aB) + 3 * 1280 + (kko)); \
        ldsm_x4(fb2[0], (bB) + 0 * 1280 + (kko)); \
        ldsm_x4(fb2[1], (bB) + 1 * 1280 + (kko)); \
        _Pragma("unroll") \
        for (int q_ = 0; q_ < 4; q_++) { \
            TFC(fa[0][q_]); TFC(fa[1][q_]); TFC(fa[2][q_]); TFC(fa[3][q_]); \
            TFC(fb2[0][q_]); TFC(fb2[1][q_]); \
        } \
    } while (0)
#define MMA_ALL do { \
        _Pragma("unroll") \
        for (int mt = 0; mt < 4; mt++) \
            _Pragma("unroll") \
            for (int nt = 0; nt < 4; nt++) { \
                unsigned bb[2] = { fb2[nt >> 1][(nt & 1) * 2], fb2[nt >> 1][(nt & 1) * 2 + 1] }; \
                mma8(acc[mt][nt], fa[mt], bb); \
            } \
    } while (0)

    for (int kt = 0; kt < nkt; kt++) {
        cp_wait<GS - 2>();
        __syncthreads();
        int cur = kt & (GS - 1);
        unsigned aB = aAddr + cur * STG;
        unsigned bB = bAddr + cur * STG;

        // prefetch tile kt+GS-1 (into stage read last iteration; all warps past barrier)
        {
            int pf = kt + GS - 1;
            bool has = pf < nkt;
            int ps = pf & (GS - 1);
            cpa16(aSt + ps * STG,      Ap + pf * 16,     aok && has);
            cpa16(aSt + ps * STG + 16, Ap + pf * 16 + 4, aok && has);
            cpa16(bSt + ps * STG,      Bp + pf * 16,     bok && has);
            cpa16(bSt + ps * STG + 16, Bp + pf * 16 + 4, bok && has);
            CP_COMMIT;
        }

        unsigned fa[4][4], fb2[2][4];
        LOADFRAG(aB, bB, 0);
        MMA_ALL;
        LOADFRAG(aB, bB, 32);
        MMA_ALL;
    }
#undef LOADFRAG
#undef MMA_ALL
#undef TFC

    // epilogue
    #pragma unroll
    for (int mt = 0; mt < 4; mt++) {
        int r0 = m0 + wm * 64 + mt * 16 + g;
        #pragma unroll
        for (int nt = 0; nt < 4; nt++) {
            int c0 = n0 + wn * 32 + nt * 8 + tig * 2;
            #pragma unroll
            for (int i = 0; i < 2; i++) {
                int rr = r0 + i * 8;
                if (rr >= M) continue;
                #pragma unroll
                for (int j = 0; j < 2; j++) {
                    int cc = c0 + j;
                    if (cc >= N) continue;
                    float v = acc[mt][nt][i * 2 + j] * alpha;
                    if (bias) v += bias[cc];
                    if (ep == 1) v = 0.5f * v * (1.0f + erff(v * 0.7071067811865476f));
                    else if (ep == 2) v += Res[(long long)rr * ldc + cc];
                    Cb[(long long)rr * ldc + cc] = v;
                }
            }
        }
    }
}

// ---------------- sigmoid over lm logits (with forced [0,0]=100) ----------------
__global__ void sigmoid_lm(float* __restrict__ lm, int total) {
    int idx = blockIdx.x * blockDim.x + threadIdx.x;
    if (idx >= total) return;
    int r = idx % (NT * NT);
    float v = (r == 0) ? 100.0f : lm[idx];
    lm[idx] = 1.0f / (1.0f + expf(-v));
}

// ---------------- fused attention: QK^T (tf32) -> softmax*gate -> AV (tf32) ----------------
#define SK 68
#define SP 204
#define SM_Q  0
#define SM_K  (SM_Q + 64*SK)
#define SM_P  (SM_K + 200*SK)
#define SM_V  (SM_P + 64*SP)
#define SM_TOT ((SM_V + 64*SP)*4)

__global__ __launch_bounds__(256, 1) void fused_attn(
    const float* __restrict__ qkv, const float* __restrict__ lm, float* __restrict__ o)
{
    extern __shared__ float sm[];
    float* Qs = sm + SM_Q;
    float* Ks = sm + SM_K;
    float* Ps = sm + SM_P;
    float* Vt = sm + SM_V;

    int tid = threadIdx.x;
    int w = tid >> 5, lane = tid & 31;
    int g = lane >> 2, tig = lane & 3;
    int qi = blockIdx.x, h = blockIdx.y, bt = blockIdx.z;
    int q0 = qi * 64;
    const float* base = qkv + (long)bt * NT * 3 * D + h * HD;

    {
        int r = tid >> 2;
        int c = (tid & 3) * 16;
        int q = q0 + r;
        if (q < NT) {
            const float* p = base + (long)q * 3 * D + c;
            #pragma unroll
            for (int j = 0; j < 4; j++) {
                float4 v = *(const float4*)(p + j * 4);
                Qs[r*SK + c + j*4 + 0] = tf32r(v.x);
                Qs[r*SK + c + j*4 + 1] = tf32r(v.y);
                Qs[r*SK + c + j*4 + 2] = tf32r(v.z);
                Qs[r*SK + c + j*4 + 3] = tf32r(v.w);
            }
        } else {
            #pragma unroll
            for (int j = 0; j < 16; j++) Qs[r*SK + c + j] = 0.f;
        }
    }
    {
        int c = (tid & 3) * 16;
        for (int r = tid >> 2; r < NT; r += 64) {
            const float* p = base + (long)r * 3 * D + D + c;
            #pragma unroll
            for (int j = 0; j < 4; j++) {
                float4 v = *(const float4*)(p + j * 4);
                Ks[r*SK + c + j*4 + 0] = tf32r(v.x);
                Ks[r*SK + c + j*4 + 1] = tf32r(v.y);
                Ks[r*SK + c + j*4 + 2] = tf32r(v.z);
                Ks[r*SK + c + j*4 + 3] = tf32r(v.w);
            }
        }
        for (int i = tid; i < 3 * 64; i += 256)
            Ks[(197 + i / 64) * SK + (i % 64)] = 0.f;
    }
    {
        int c4 = (tid & 15) * 4;
        for (int m = tid >> 4; m < NT; m += 16) {
            float4 v = *(const float4*)(base + (long)m * 3 * D + 2 * D + c4);
            Vt[(c4 + 0) * SP + m] = tf32r(v.x);
            Vt[(c4 + 1) * SP + m] = tf32r(v.y);
            Vt[(c4 + 2) * SP + m] = tf32r(v.z);
            Vt[(c4 + 3) * SP + m] = tf32r(v.w);
        }
        for (int i = tid; i < 64 * 7; i += 256)
            Vt[(i / 7) * SP + 197 + (i % 7)] = 0.f;
    }
    __syncthreads();

    {
        int wm = w & 3;
        int wn = w >> 2;
        int nt0 = wn ? 13 : 0, nt1 = wn ? 25 : 13;
        for (int nt = nt0; nt < nt1; nt++) {
            float c[4] = {0.f, 0.f, 0.f, 0.f};
            #pragma unroll
            for (int kk = 0; kk < 64; kk += 8) {
                unsigned a[4], b[2];
                int ra = wm * 16 + g;
                a[0] = __float_as_uint(Qs[ra*SK + kk + tig]);
                a[1] = __float_as_uint(Qs[(ra + 8)*SK + kk + tig]);
                a[2] = __float_as_uint(Qs[ra*SK + kk + tig + 4]);
                a[3] = __float_as_uint(Qs[(ra + 8)*SK + kk + tig + 4]);
                int rb = nt * 8 + g;
                b[0] = __float_as_uint(Ks[rb*SK + kk + tig]);
                b[1] = __float_as_uint(Ks[rb*SK + kk + tig + 4]);
                mma8(c, a, b);
            }
            int rm = wm * 16 + g, cn = nt * 8 + tig * 2;
            Ps[rm*SP + cn] = c[0];       Ps[rm*SP + cn + 1] = c[1];
            Ps[(rm+8)*SP + cn] = c[2];   Ps[(rm+8)*SP + cn + 1] = c[3];
        }
    }
    __syncthreads();

    {
        for (int rr = 0; rr < 8; rr++) {
            int r = (w << 3) + rr;
            int q = q0 + r;
            if (q < NT) {
                const float* lmr = lm + ((long)bt * NT + q) * NT;
                float mx = -1e30f;
                for (int k = lane; k < NT; k += 32) mx = fmaxf(mx, Ps[r*SP + k]);
                #pragma unroll
                for (int s = 16; s > 0; s >>= 1) mx = fmaxf(mx, __shfl_xor_sync(0xffffffffu, mx, s));
                float sum = 0.f;
                for (int k = lane; k < NT; k += 32) {
                    float e = expf(0.125f * (Ps[r*SP + k] - mx));
                    Ps[r*SP + k] = e;
                    sum += e;
                }
                #pragma unroll
                for (int s = 16; s > 0; s >>= 1) sum += __shfl_xor_sync(0xffffffffu, sum, s);
                float inv = 1.0f / sum;
                for (int k = lane; k < 204; k += 32) {
                    float p = (k < NT) ? tf32r(Ps[r*SP + k] * inv * lmr[k]) : 0.f;
                    Ps[r*SP + k] = p;
                }
            } else {
                for (int k = lane; k < 204; k += 32) Ps[r*SP + k] = 0.f;
            }
        }
    }
    __syncthreads();

    {
        int wmA = w >> 1;
        int wnA = w & 1;
        float acc[4][4];
        #pragma unroll
        for (int nt = 0; nt < 4; nt++)
            #pragma unroll
            for (int i = 0; i < 4; i++) acc[nt][i] = 0.f;

        for (int kk = 0; kk < 200; kk += 8) {
            unsigned a[4], b[4][2];
            int ra = wmA * 16 + g;
            a[0] = __float_as_uint(Ps[ra*SP + kk + tig]);
            a[1] = __float_as_uint(Ps[(ra + 8)*SP + kk + tig]);
            a[2] = __float_as_uint(Ps[ra*SP + kk + tig + 4]);
            a[3] = __float_as_uint(Ps[(ra + 8)*SP + kk + tig + 4]);
            #pragma unroll
            for (int nt = 0; nt < 4; nt++) {
                int rb = wnA * 32 + nt * 8 + g;
                b[nt][0] = __float_as_uint(Vt[rb*SP + kk + tig]);
                b[nt][1] = __float_as_uint(Vt[rb*SP + kk + tig + 4]);
            }
            #pragma unroll
            for (int nt = 0; nt < 4; nt++) mma8(acc[nt], a, b[nt]);
        }

        #pragma unroll
        for (int nt = 0; nt < 4; nt++) {
            int cn = wnA * 32 + nt * 8 + tig * 2;
            #pragma unroll
            for (int i = 0; i < 2; i++) {
                int q = q0 + wmA * 16 + g + i * 8;
                if (q >= NT) continue;
                float* op = o + ((long)bt * NT + q) * D + h * HD + cn;
                op[0] = acc[nt][i * 2];
                op[1] = acc[nt][i * 2 + 1];
            }
        }
    }
}

// ---------------- fused scatter(+residual) + LayerNorm2: y, xn ----------------
__global__ void scatter_ln(const float* __restrict__ x, const float* __restrict__ op,
                           const float* __restrict__ g, const float* __restrict__ be,
                           float* __restrict__ y, float* __restrict__ xn) {
    int row = blockIdx.x;
    int tid = threadIdx.x;
    int p = row % ST;
    int b = row / ST;
    float v[3];
    #pragma unroll
    for (int c = 0; c < 3; c++) {
        int d = tid + c * 256;
        float add;
        if (p == 0) {
            float s = 0.f;
            #pragma unroll
            for (int t = 0; t < TT; t++)
                s += op[((long)((b * TT + t) * NT)) * D + d];
            add = s * (1.0f / TT);
        } else {
            int q = p - 1;
            int hw = q / TT, t = q % TT;
            add = op[((long)((b * TT + t) * NT + 1 + hw)) * D + d];
        }
        v[c] = x[(long)row * D + d] + add;
        y[(long)row * D + d] = v[c];
    }
    __shared__ float red[256];
    red[tid] = v[0] + v[1] + v[2];
    __syncthreads();
    for (int o = 128; o > 0; o >>= 1) { if (tid < o) red[tid] += red[tid + o]; __syncthreads(); }
    float mean = red[0] * (1.0f / D);
    __syncthreads();
    float d0 = v[0] - mean, d1 = v[1] - mean, d2 = v[2] - mean;
    red[tid] = d0*d0 + d1*d1 + d2*d2;
    __syncthreads();
    for (int o = 128; o > 0; o >>= 1) { if (tid < o) red[tid] += red[tid + o]; __syncthreads(); }
    float rs = rsqrtf(red[0] * (1.0f / D) + 1e-5f);
    float* yr = xn + (long)row * D;
    yr[tid]       = d0 * rs * g[tid]       + be[tid];
    yr[tid + 256] = d1 * rs * g[tid + 256] + be[tid + 256];
    yr[tid + 512] = d2 * rs * g[tid + 512] + be[tid + 512];
}

// ---------------- launcher ----------------
extern "C" void kernel_launch(void* const* d_in, const int* in_sizes, int n_in,
                              void* d_out, int out_size) {
    const float* x    = (const float*)d_in[0];
    const float* Wmq  = (const float*)d_in[1];
    const float* bmq  = (const float*)d_in[2];
    const float* Wmk  = (const float*)d_in[3];
    const float* bmk  = (const float*)d_in[4];
    const float* g1   = (const float*)d_in[5];
    const float* be1  = (const float*)d_in[6];
    const float* Wqkv = (const float*)d_in[7];
    const float* Wpr  = (const float*)d_in[8];
    const float* bpr  = (const float*)d_in[9];
    const float* g2   = (const float*)d_in[10];
    const float* be2  = (const float*)d_in[11];
    const float* Wf1  = (const float*)d_in[12];
    const float* bf1  = (const float*)d_in[13];
    const float* Wf2  = (const float*)d_in[14];
    const float* bf2  = (const float*)d_in[15];

    float* out = (float*)d_out;
    float* y   = out;
    float* lm  = out + YSZ;

    float *xt, *qmk, *wqk, *bqk, *xn, *qkv, *o, *op, *h;
    cudaGetSymbolAddress((void**)&xt,  g_xt);
    cudaGetSymbolAddress((void**)&qmk, g_qmk);
    cudaGetSymbolAddress((void**)&wqk, g_wqk);
    cudaGetSymbolAddress((void**)&bqk, g_bqk);
    cudaGetSymbolAddress((void**)&xn,  g_xn);
    cudaGetSymbolAddress((void**)&qkv, g_qkv);
    cudaGetSymbolAddress((void**)&o,   g_o);
    cudaGetSymbolAddress((void**)&op,  g_op);
    cudaGetSymbolAddress((void**)&h,   g_h);

    static int smem_set = 0;
    if (!smem_set) {
        cudaFuncSetAttribute(fused_attn, cudaFuncAttributeMaxDynamicSharedMemorySize, SM_TOT);
        cudaFuncSetAttribute(gemm_tf32, cudaFuncAttributeMaxDynamicSharedMemorySize, SMEM_G);
        smem_set = 1;
    }

    int gy  = (MXT + 127) / 128;   // 99
    int gy2 = (MY  + 127) / 128;   // 99

    // 1) gather + LN1; concat mask weights
    gather_ln<<<MXT, 256>>>(x, g1, be1, xt, xn);
    concat_qk<<<(2 * D * D + 255) / 256, 256>>>(Wmq, Wmk, bmq, bmk, wqk, bqk);

    // 2) fused mask projections [qm|km]
    gemm_tf32<<<dim3((2*D)/128, gy), 256, SMEM_G>>>(xt, wqk, bqk, nullptr, qmk, MXT, 2*D, D,
                                                    D, D, 2*D, 1,0,0,0,0,0, 1.0f, 0);

    // 3) lm logits (batched over bt), sigmoid with forced [0,0]=100
    gemm_tf32<<<dim3(2, 2, BT), 256, SMEM_G>>>(qmk, qmk + D, nullptr, nullptr, lm, NT, NT, D,
                                               2*D, 2*D, NT,
                                               1, 0, 0, (long long)NT*2*D, (long long)NT*2*D,
                                               (long long)NT*NT, 1.0f, 0);
    sigmoid_lm<<<(LMSZ + 255) / 256, 256>>>(lm, LMSZ);

    // 4) QKV projection (no bias)
    gemm_tf32<<<dim3((3*D)/128, gy), 256, SMEM_G>>>(xn, Wqkv, nullptr, nullptr, qkv, MXT, 3*D, D,
                                                    D, D, 3*D, 1,0,0,0,0,0, 1.0f, 0);

    // 5) fused attention (QK^T + softmax*gate + AV)
    fused_attn<<<dim3(4, NHD, BT), 256, SM_TOT>>>(qkv, lm, o);

    // 6) output projection, scatter back (+residual) + LN2
    gemm_tf32<<<dim3(D/128, gy), 256, SMEM_G>>>(o, Wpr, bpr, nullptr, op, MXT, D, D,
                                                D, D, D, 1,0,0,0,0,0, 1.0f, 0);
    scatter_ln<<<MY, 256>>>(x, op, g2, be2, y, xn);

    // 7) MLP: fc1(+gelu) -> fc2(+residual into y)
    gemm_tf32<<<dim3(DH/128, gy2), 256, SMEM_G>>>(xn, Wf1, bf1, nullptr, h, MY, DH, D,
                                                  D, D, DH, 1,0,0,0,0,0, 1.0f, 1);
    gemm_tf32<<<dim3(D/128, gy2), 256, SMEM_G>>>(h, Wf2, bf2, y, y, MY, D, DH,
                                                 DH, DH, D, 1,0,0,0,0,0, 1.0f, 2);
}

// round 6
// speedup vs baseline: 1.3114x; 1.0603x over previous
#include <cuda_runtime.h>
#include <math.h>

// ---------------- problem constants ----------------
#define D    768
#define DH   3072
#define BB   8
#define TT   8
#define NT   197            // tokens per frame (cls + 196)
#define BT   64             // B*T
#define NHD  12             // heads
#define HD   64             // head dim
#define ST   1569           // T*H*W + 1
#define MXT  (BT*NT)        // 12608 rows in frame-token space
#define MY   (BB*ST)        // 12552 rows in original token space
#define YSZ  (MY*D)         // 9,639,936
#define LMSZ (BT*NT*NT)     // 2,483,776

#define GS   4              // cp.async pipeline stages
#define SMEM_G (GS*2*128*20*4)   // 81920 bytes

// ---------------- scratch (device globals: allocation-free) ----------------
__device__ float g_xt [MXT*D];
__device__ float g_qmk[MXT*2*D];      // [qm | km] fused
__device__ float g_wqk[2*D*D];        // [Wmq ; Wmk] (tf32-rounded)
__device__ float g_bqk[2*D];
__device__ float g_xn [MXT*D];        // LN1 out, later LN2 out (tf32-rounded)
__device__ float g_qkv[MXT*3*D];
__device__ float g_o  [MXT*D];
__device__ float g_op [MXT*D];
__device__ float g_h  [MY*DH];
__device__ float g_wqkv[3*D*D];       // tf32-rounded weight copies
__device__ float g_wpr [D*D];
__device__ float g_wf1 [DH*D];
__device__ float g_wf2 [D*DH];

// ---------------- helpers ----------------
__device__ __forceinline__ float tf32r(float x) {
    unsigned r;
    asm("cvt.rna.tf32.f32 %0, %1;" : "=r"(r) : "f"(x));
    return __uint_as_float(r);
}

__device__ __forceinline__ void mma8(float* c, const unsigned* a, const unsigned* b) {
    asm volatile(
        "mma.sync.aligned.m16n8k8.row.col.f32.tf32.tf32.f32 "
        "{%0,%1,%2,%3}, {%4,%5,%6,%7}, {%8,%9}, {%0,%1,%2,%3};"
        : "+f"(c[0]), "+f"(c[1]), "+f"(c[2]), "+f"(c[3])
        : "r"(a[0]), "r"(a[1]), "r"(a[2]), "r"(a[3]), "r"(b[0]), "r"(b[1]));
}

__device__ __forceinline__ void ldsm_x4(unsigned* r, unsigned addr) {
    asm volatile("ldmatrix.sync.aligned.m8n8.x4.shared.b16 {%0,%1,%2,%3}, [%4];"
        : "=r"(r[0]), "=r"(r[1]), "=r"(r[2]), "=r"(r[3]) : "r"(addr));
}

__device__ __forceinline__ void cpa16(unsigned dst, const float* src, bool p) {
    asm volatile("cp.async.cg.shared.global [%0], [%1], 16, %2;"
        :: "r"(dst), "l"(src), "r"(p ? 16 : 0));
}
#define CP_COMMIT asm volatile("cp.async.commit_group;")
template<int N> __device__ __forceinline__ void cp_wait() {
    asm volatile("cp.async.wait_group %0;" :: "n"(N));
}

// ---------------- round-copy weights to tf32 ----------------
__global__ void round_copy(const float* __restrict__ src, float* __restrict__ dst, int n) {
    int i = blockIdx.x * blockDim.x + threadIdx.x;
    if (i < n) dst[i] = tf32r(src[i]);
}

// ---------------- concat Wmq/Wmk -> wqk (rounded), bmq/bmk -> bqk ----------------
__global__ void concat_qk(const float* __restrict__ Wmq, const float* __restrict__ Wmk,
                          const float* __restrict__ bmq, const float* __restrict__ bmk,
                          float* __restrict__ W, float* __restrict__ b2) {
    int i = blockIdx.x * blockDim.x + threadIdx.x;
    const int half = D * D;
    if (i < half) W[i] = tf32r(Wmq[i]);
    else if (i < 2 * half) W[i] = tf32r(Wmk[i - half]);
    if (i < D) b2[i] = bmq[i];
    else if (i < 2 * D) b2[i] = bmk[i - D];
}

// ---------------- fused gather + LayerNorm1: x -> xt(tf32), xn(tf32) ----------------
__global__ void gather_ln(const float* __restrict__ x, const float* __restrict__ g,
                          const float* __restrict__ be,
                          float* __restrict__ xt, float* __restrict__ xn) {
    int row = blockIdx.x;
    int tid = threadIdx.x;
    int n  = row % NT;
    int bt = row / NT;
    int b = bt / TT, t = bt % TT;
    int src = (n == 0) ? (b * ST) : (b * ST + 1 + (n - 1) * TT + t);
    const float* xr = x + (long)src * D;
    float v0 = xr[tid], v1 = xr[tid + 256], v2 = xr[tid + 512];
    float* xtr = xt + (long)row * D;
    xtr[tid] = tf32r(v0); xtr[tid + 256] = tf32r(v1); xtr[tid + 512] = tf32r(v2);

    __shared__ float red[256];
    red[tid] = v0 + v1 + v2;
    __syncthreads();
    for (int o = 128; o > 0; o >>= 1) { if (tid < o) red[tid] += red[tid + o]; __syncthreads(); }
    float mean = red[0] * (1.0f / D);
    __syncthreads();
    float d0 = v0 - mean, d1 = v1 - mean, d2 = v2 - mean;
    red[tid] = d0*d0 + d1*d1 + d2*d2;
    __syncthreads();
    for (int o = 128; o > 0; o >>= 1) { if (tid < o) red[tid] += red[tid + o]; __syncthreads(); }
    float rs = rsqrtf(red[0] * (1.0f / D) + 1e-5f);
    float* yr = xn + (long)row * D;
    yr[tid]       = tf32r(d0 * rs * g[tid]       + be[tid]);
    yr[tid + 256] = tf32r(d1 * rs * g[tid + 256] + be[tid + 256]);
    yr[tid + 512] = tf32r(d2 * rs * g[tid + 512] + be[tid + 512]);
}

// ---------------- universal tf32 GEMM: cp.async 4-stage + ldmatrix ----------------
// Inputs must already be tf32-rounded. C = epi(alpha*A*B^T + bias).
// ep bits: low 2 = 0:+bias 1:+bias,gelu 2:+bias,+Res ; bit 2 (4) = round output to tf32
__global__ __launch_bounds__(256, 2) void gemm_tf32(
    const float* __restrict__ A, const float* __restrict__ B,
    const float* __restrict__ bias, const float* __restrict__ Res,
    float* __restrict__ C, int M, int N, int K,
    int lda, int ldb, int ldc,
    int inner, int sAi, int sBi, long long sAo, long long sBo, long long sC,
    float alpha, int ep)
{
    extern __shared__ __align__(16) float dyn[];   // A stages then B stages

    int tid  = threadIdx.x;
    int warp = tid >> 5, lane = tid & 31;
    int g = lane >> 2, tig = lane & 3;
    int wm = warp >> 2;     // 0..1 : 64 rows
    int wn = warp & 3;      // 0..3 : 32 cols
    int m0 = blockIdx.y * 128, n0 = blockIdx.x * 128;

    const float* Ab = A;
    const float* Bb = B;
    float* Cb = C;
    if (sC) {
        int z = blockIdx.z;
        int zo = z / inner, zi = z % inner;
        Ab += (long long)zo * sAo + (long long)zi * sAi;
        Bb += (long long)zo * sBo + (long long)zi * sBi;
        Cb += (long long)z * sC;
    }

    int ldrow = tid >> 1;          // 0..127
    int ldcol = (tid & 1) * 8;     // 0 or 8
    bool aok = (m0 + ldrow) < M;
    bool bok = (n0 + ldrow) < N;
    const float* Ap = Ab + (long long)(m0 + ldrow) * lda + ldcol;
    const float* Bp = Bb + (long long)(n0 + ldrow) * ldb + ldcol;

    unsigned smB = (unsigned)__cvta_generic_to_shared(dyn);
    const unsigned STG = 128 * 20 * 4;            // 10240 bytes per stage
    unsigned aSt = smB + (ldrow * 20 + ldcol) * 4;
    unsigned bSt = smB + GS * STG + (ldrow * 20 + ldcol) * 4;

    // ldmatrix per-thread addresses
    int arow = lane & 15;
    int acol = (lane >> 4) * 4;
    int brow = (lane & 7) + ((lane & 16) >> 1);
    int bcol = ((lane >> 3) & 1) * 4;
    unsigned aAddr = smB + ((wm * 64 + arow) * 20 + acol) * 4;
    unsigned bAddr = smB + GS * STG + ((wn * 32 + brow) * 20 + bcol) * 4;

    float acc[4][4][4];
    #pragma unroll
    for (int mt = 0; mt < 4; mt++)
        #pragma unroll
        for (int nt = 0; nt < 4; nt++)
            #pragma unroll
            for (int i = 0; i < 4; i++) acc[mt][nt][i] = 0.f;

    int nkt = K >> 4;

    // prologue: prefetch GS-1 tiles
    #pragma unroll
    for (int s = 0; s < GS - 1; s++) {
        bool has = s < nkt;
        cpa16(aSt + s * STG,      Ap + s * 16,     aok && has);
        cpa16(aSt + s * STG + 16, Ap + s * 16 + 4, aok && has);
        cpa16(bSt + s * STG,      Bp + s * 16,     bok && has);
        cpa16(bSt + s * STG + 16, Bp + s * 16 + 4, bok && has);
        CP_COMMIT;
    }

#define LOADFRAG(aB, bB, kko) do { \
        ldsm_x4(fa[0], (aB) + 0 * 1280 + (kko)); \
        ldsm_x4(fa[1], (aB) + 1 * 1280 + (kko)); \
        ldsm_x4(fa[2], (aB) + 2 * 1280 + (kko)); \
        ldsm_x4(fa[3], (aB) + 3 * 1280 + (kko)); \
        ldsm_x4(fb2[0], (bB) + 0 * 1280 + (kko)); \
        ldsm_x4(fb2[1], (bB) + 1 * 1280 + (kko)); \
    } while (0)
#define MMA_ALL do { \
        _Pragma("unroll") \
        for (int mt = 0; mt < 4; mt++) \
            _Pragma("unroll") \
            for (int nt = 0; nt < 4; nt++) { \
                unsigned bb[2] = { fb2[nt >> 1][(nt & 1) * 2], fb2[nt >> 1][(nt & 1) * 2 + 1] }; \
                mma8(acc[mt][nt], fa[mt], bb); \
            } \
    } while (0)

    for (int kt = 0; kt < nkt; kt++) {
        cp_wait<GS - 2>();
        __syncthreads();
        int cur = kt & (GS - 1);
        unsigned aB = aAddr + cur * STG;
        unsigned bB = bAddr + cur * STG;

        {
            int pf = kt + GS - 1;
            bool has = pf < nkt;
            int ps = pf & (GS - 1);
            cpa16(aSt + ps * STG,      Ap + pf * 16,     aok && has);
            cpa16(aSt + ps * STG + 16, Ap + pf * 16 + 4, aok && has);
            cpa16(bSt + ps * STG,      Bp + pf * 16,     bok && has);
            cpa16(bSt + ps * STG + 16, Bp + pf * 16 + 4, bok && has);
            CP_COMMIT;
        }

        unsigned fa[4][4], fb2[2][4];
        LOADFRAG(aB, bB, 0);
        MMA_ALL;
        LOADFRAG(aB, bB, 32);
        MMA_ALL;
    }
#undef LOADFRAG
#undef MMA_ALL

    int base_ep = ep & 3;
    bool rnd = (ep & 4) != 0;

    // epilogue
    #pragma unroll
    for (int mt = 0; mt < 4; mt++) {
        int r0 = m0 + wm * 64 + mt * 16 + g;
        #pragma unroll
        for (int nt = 0; nt < 4; nt++) {
            int c0 = n0 + wn * 32 + nt * 8 + tig * 2;
            #pragma unroll
            for (int i = 0; i < 2; i++) {
                int rr = r0 + i * 8;
                if (rr >= M) continue;
                #pragma unroll
                for (int j = 0; j < 2; j++) {
                    int cc = c0 + j;
                    if (cc >= N) continue;
                    float v = acc[mt][nt][i * 2 + j] * alpha;
                    if (bias) v += bias[cc];
                    if (base_ep == 1) v = 0.5f * v * (1.0f + erff(v * 0.7071067811865476f));
                    else if (base_ep == 2) v += Res[(long long)rr * ldc + cc];
                    if (rnd) v = tf32r(v);
                    Cb[(long long)rr * ldc + cc] = v;
                }
            }
        }
    }
}

// ---------------- sigmoid over lm logits (with forced [0,0]=100) ----------------
__global__ void sigmoid_lm(float* __restrict__ lm, int total) {
    int idx = blockIdx.x * blockDim.x + threadIdx.x;
    if (idx >= total) return;
    int r = idx % (NT * NT);
    float v = (r == 0) ? 100.0f : lm[idx];
    lm[idx] = 1.0f / (1.0f + expf(-v));
}

// ---------------- fused attention: QK^T (tf32) -> softmax*gate -> AV (tf32) ----------------
// qkv is pre-rounded to tf32.
#define SK 68
#define SP 204
#define SM_Q  0
#define SM_K  (SM_Q + 64*SK)
#define SM_P  (SM_K + 200*SK)
#define SM_V  (SM_P + 64*SP)
#define SM_TOT ((SM_V + 64*SP)*4)

__global__ __launch_bounds__(256, 1) void fused_attn(
    const float* __restrict__ qkv, const float* __restrict__ lm, float* __restrict__ o)
{
    extern __shared__ float sm[];
    float* Qs = sm + SM_Q;
    float* Ks = sm + SM_K;
    float* Ps = sm + SM_P;
    float* Vt = sm + SM_V;

    int tid = threadIdx.x;
    int w = tid >> 5, lane = tid & 31;
    int g = lane >> 2, tig = lane & 3;
    int qi = blockIdx.x, h = blockIdx.y, bt = blockIdx.z;
    int q0 = qi * 64;
    const float* base = qkv + (long)bt * NT * 3 * D + h * HD;

    {
        int r = tid >> 2;
        int c = (tid & 3) * 16;
        int q = q0 + r;
        if (q < NT) {
            const float* p = base + (long)q * 3 * D + c;
            #pragma unroll
            for (int j = 0; j < 4; j++)
                *(float4*)&Qs[r*SK + c + j*4] = *(const float4*)(p + j * 4);
        } else {
            #pragma unroll
            for (int j = 0; j < 16; j++) Qs[r*SK + c + j] = 0.f;
        }
    }
    {
        int c = (tid & 3) * 16;
        for (int r = tid >> 2; r < NT; r += 64) {
            const float* p = base + (long)r * 3 * D + D + c;
            #pragma unroll
            for (int j = 0; j < 4; j++)
                *(float4*)&Ks[r*SK + c + j*4] = *(const float4*)(p + j * 4);
        }
        for (int i = tid; i < 3 * 64; i += 256)
            Ks[(197 + i / 64) * SK + (i % 64)] = 0.f;
    }
    {
        int c4 = (tid & 15) * 4;
        for (int m = tid >> 4; m < NT; m += 16) {
            float4 v = *(const float4*)(base + (long)m * 3 * D + 2 * D + c4);
            Vt[(c4 + 0) * SP + m] = v.x;
            Vt[(c4 + 1) * SP + m] = v.y;
            Vt[(c4 + 2) * SP + m] = v.z;
            Vt[(c4 + 3) * SP + m] = v.w;
        }
        for (int i = tid; i < 64 * 7; i += 256)
            Vt[(i / 7) * SP + 197 + (i % 7)] = 0.f;
    }
    __syncthreads();

    {
        int wm = w & 3;
        int wn = w >> 2;
        int nt0 = wn ? 13 : 0, nt1 = wn ? 25 : 13;
        for (int nt = nt0; nt < nt1; nt++) {
            float c[4] = {0.f, 0.f, 0.f, 0.f};
            #pragma unroll
            for (int kk = 0; kk < 64; kk += 8) {
                unsigned a[4], b[2];
                int ra = wm * 16 + g;
                a[0] = __float_as_uint(Qs[ra*SK + kk + tig]);
                a[1] = __float_as_uint(Qs[(ra + 8)*SK + kk + tig]);
                a[2] = __float_as_uint(Qs[ra*SK + kk + tig + 4]);
                a[3] = __float_as_uint(Qs[(ra + 8)*SK + kk + tig + 4]);
                int rb = nt * 8 + g;
                b[0] = __float_as_uint(Ks[rb*SK + kk + tig]);
                b[1] = __float_as_uint(Ks[rb*SK + kk + tig + 4]);
                mma8(c, a, b);
            }
            int rm = wm * 16 + g, cn = nt * 8 + tig * 2;
            Ps[rm*SP + cn] = c[0];       Ps[rm*SP + cn + 1] = c[1];
            Ps[(rm+8)*SP + cn] = c[2];   Ps[(rm+8)*SP + cn + 1] = c[3];
        }
    }
    __syncthreads();

    {
        for (int rr = 0; rr < 8; rr++) {
            int r = (w << 3) + rr;
            int q = q0 + r;
            if (q < NT) {
                const float* lmr = lm + ((long)bt * NT + q) * NT;
                float mx = -1e30f;
                for (int k = lane; k < NT; k += 32) mx = fmaxf(mx, Ps[r*SP + k]);
                #pragma unroll
                for (int s = 16; s > 0; s >>= 1) mx = fmaxf(mx, __shfl_xor_sync(0xffffffffu, mx, s));
                float sum = 0.f;
                for (int k = lane; k < NT; k += 32) {
                    float e = expf(0.125f * (Ps[r*SP + k] - mx));
                    Ps[r*SP + k] = e;
                    sum += e;
                }
                #pragma unroll
                for (int s = 16; s > 0; s >>= 1) sum += __shfl_xor_sync(0xffffffffu, sum, s);
                float inv = 1.0f / sum;
                for (int k = lane; k < 204; k += 32) {
                    float p = (k < NT) ? tf32r(Ps[r*SP + k] * inv * lmr[k]) : 0.f;
                    Ps[r*SP + k] = p;
                }
            } else {
                for (int k = lane; k < 204; k += 32) Ps[r*SP + k] = 0.f;
            }
        }
    }
    __syncthreads();

    {
        int wmA = w >> 1;
        int wnA = w & 1;
        float acc[4][4];
        #pragma unroll
        for (int nt = 0; nt < 4; nt++)
            #pragma unroll
            for (int i = 0; i < 4; i++) acc[nt][i] = 0.f;

        for (int kk = 0; kk < 200; kk += 8) {
            unsigned a[4], b[4][2];
            int ra = wmA * 16 + g;
            a[0] = __float_as_uint(Ps[ra*SP + kk + tig]);
            a[1] = __float_as_uint(Ps[(ra + 8)*SP + kk + tig]);
            a[2] = __float_as_uint(Ps[ra*SP + kk + tig + 4]);
            a[3] = __float_as_uint(Ps[(ra + 8)*SP + kk + tig + 4]);
            #pragma unroll
            for (int nt = 0; nt < 4; nt++) {
                int rb = wnA * 32 + nt * 8 + g;
                b[nt][0] = __float_as_uint(Vt[rb*SP + kk + tig]);
                b[nt][1] = __float_as_uint(Vt[rb*SP + kk + tig + 4]);
            }
            #pragma unroll
            for (int nt = 0; nt < 4; nt++) mma8(acc[nt], a, b[nt]);
        }

        #pragma unroll
        for (int nt = 0; nt < 4; nt++) {
            int cn = wnA * 32 + nt * 8 + tig * 2;
            #pragma unroll
            for (int i = 0; i < 2; i++) {
                int q = q0 + wmA * 16 + g + i * 8;
                if (q >= NT) continue;
                float* op = o + ((long)bt * NT + q) * D + h * HD + cn;
                op[0] = tf32r(acc[nt][i * 2]);       // o feeds proj GEMM
                op[1] = tf32r(acc[nt][i * 2 + 1]);
            }
        }
    }
}

// ---------------- fused scatter(+residual) + LayerNorm2: y, xn(tf32) ----------------
__global__ void scatter_ln(const float* __restrict__ x, const float* __restrict__ op,
                           const float* __restrict__ g, const float* __restrict__ be,
                           float* __restrict__ y, float* __restrict__ xn) {
    int row = blockIdx.x;
    int tid = threadIdx.x;
    int p = row % ST;
    int b = row / ST;
    float v[3];
    #pragma unroll
    for (int c = 0; c < 3; c++) {
        int d = tid + c * 256;
        float add;
        if (p == 0) {
            float s = 0.f;
            #pragma unroll
            for (int t = 0; t < TT; t++)
                s += op[((long)((b * TT + t) * NT)) * D + d];
            add = s * (1.0f / TT);
        } else {
            int q = p - 1;
            int hw = q / TT, t = q % TT;
            add = op[((long)((b * TT + t) * NT + 1 + hw)) * D + d];
        }
        v[c] = x[(long)row * D + d] + add;
        y[(long)row * D + d] = v[c];
    }
    __shared__ float red[256];
    red[tid] = v[0] + v[1] + v[2];
    __syncthreads();
    for (int o = 128; o > 0; o >>= 1) { if (tid < o) red[tid] += red[tid + o]; __syncthreads(); }
    float mean = red[0] * (1.0f / D);
    __syncthreads();
    float d0 = v[0] - mean, d1 = v[1] - mean, d2 = v[2] - mean;
    red[tid] = d0*d0 + d1*d1 + d2*d2;
    __syncthreads();
    for (int o = 128; o > 0; o >>= 1) { if (tid < o) red[tid] += red[tid + o]; __syncthreads(); }
    float rs = rsqrtf(red[0] * (1.0f / D) + 1e-5f);
    float* yr = xn + (long)row * D;
    yr[tid]       = tf32r(d0 * rs * g[tid]       + be[tid]);
    yr[tid + 256] = tf32r(d1 * rs * g[tid + 256] + be[tid + 256]);
    yr[tid + 512] = tf32r(d2 * rs * g[tid + 512] + be[tid + 512]);
}

// ---------------- launcher ----------------
extern "C" void kernel_launch(void* const* d_in, const int* in_sizes, int n_in,
                              void* d_out, int out_size) {
    const float* x    = (const float*)d_in[0];
    const float* Wmq  = (const float*)d_in[1];
    const float* bmq  = (const float*)d_in[2];
    const float* Wmk  = (const float*)d_in[3];
    const float* bmk  = (const float*)d_in[4];
    const float* g1   = (const float*)d_in[5];
    const float* be1  = (const float*)d_in[6];
    const float* Wqkv = (const float*)d_in[7];
    const float* Wpr  = (const float*)d_in[8];
    const float* bpr  = (const float*)d_in[9];
    const float* g2   = (const float*)d_in[10];
    const float* be2  = (const float*)d_in[11];
    const float* Wf1  = (const float*)d_in[12];
    const float* bf1  = (const float*)d_in[13];
    const float* Wf2  = (const float*)d_in[14];
    const float* bf2  = (const float*)d_in[15];

    float* out = (float*)d_out;
    float* y   = out;
    float* lm  = out + YSZ;

    float *xt, *qmk, *wqk, *bqk, *xn, *qkv, *o, *op, *h;
    float *wqkv, *wpr, *wf1, *wf2;
    cudaGetSymbolAddress((void**)&xt,  g_xt);
    cudaGetSymbolAddress((void**)&qmk, g_qmk);
    cudaGetSymbolAddress((void**)&wqk, g_wqk);
    cudaGetSymbolAddress((void**)&bqk, g_bqk);
    cudaGetSymbolAddress((void**)&xn,  g_xn);
    cudaGetSymbolAddress((void**)&qkv, g_qkv);
    cudaGetSymbolAddress((void**)&o,   g_o);
    cudaGetSymbolAddress((void**)&op,  g_op);
    cudaGetSymbolAddress((void**)&h,   g_h);
    cudaGetSymbolAddress((void**)&wqkv,g_wqkv);
    cudaGetSymbolAddress((void**)&wpr, g_wpr);
    cudaGetSymbolAddress((void**)&wf1, g_wf1);
    cudaGetSymbolAddress((void**)&wf2, g_wf2);

    static int smem_set = 0;
    if (!smem_set) {
        cudaFuncSetAttribute(fused_attn, cudaFuncAttributeMaxDynamicSharedMemorySize, SM_TOT);
        cudaFuncSetAttribute(gemm_tf32, cudaFuncAttributeMaxDynamicSharedMemorySize, SMEM_G);
        smem_set = 1;
    }

    int gy  = (MXT + 127) / 128;   // 99
    int gy2 = (MY  + 127) / 128;   // 99

    // 0) pre-round weights to tf32 (scratch copies)
    round_copy<<<(3*D*D + 255) / 256, 256>>>(Wqkv, wqkv, 3*D*D);
    round_copy<<<(D*D + 255) / 256, 256>>>(Wpr, wpr, D*D);
    round_copy<<<(DH*D + 255) / 256, 256>>>(Wf1, wf1, DH*D);
    round_copy<<<(D*DH + 255) / 256, 256>>>(Wf2, wf2, D*DH);
    concat_qk<<<(2 * D * D + 255) / 256, 256>>>(Wmq, Wmk, bmq, bmk, wqk, bqk);

    // 1) gather + LN1 (tf32-rounded outputs)
    gather_ln<<<MXT, 256>>>(x, g1, be1, xt, xn);

    // 2) fused mask projections [qm|km] (round output: feeds lm GEMM)
    gemm_tf32<<<dim3((2*D)/128, gy), 256, SMEM_G>>>(xt, wqk, bqk, nullptr, qmk, MXT, 2*D, D,
                                                    D, D, 2*D, 1,0,0,0,0,0, 1.0f, 0 | 4);

    // 3) lm logits (batched over bt), sigmoid with forced [0,0]=100
    gemm_tf32<<<dim3(2, 2, BT), 256, SMEM_G>>>(qmk, qmk + D, nullptr, nullptr, lm, NT, NT, D,
                                               2*D, 2*D, NT,
                                               1, 0, 0, (long long)NT*2*D, (long long)NT*2*D,
                                               (long long)NT*NT, 1.0f, 0);
    sigmoid_lm<<<(LMSZ + 255) / 256, 256>>>(lm, LMSZ);

    // 4) QKV projection (round output: feeds attention MMAs)
    gemm_tf32<<<dim3((3*D)/128, gy), 256, SMEM_G>>>(xn, wqkv, nullptr, nullptr, qkv, MXT, 3*D, D,
                                                    D, D, 3*D, 1,0,0,0,0,0, 1.0f, 0 | 4);

    // 5) fused attention (QK^T + softmax*gate + AV), rounds o
    fused_attn<<<dim3(4, NHD, BT), 256, SM_TOT>>>(qkv, lm, o);

    // 6) output projection, scatter back (+residual) + LN2
    gemm_tf32<<<dim3(D/128, gy), 256, SMEM_G>>>(o, wpr, bpr, nullptr, op, MXT, D, D,
                                                D, D, D, 1,0,0,0,0,0, 1.0f, 0);
    scatter_ln<<<MY, 256>>>(x, op, g2, be2, y, xn);

    // 7) MLP: fc1(+gelu, round: feeds fc2) -> fc2(+residual into y)
    gemm_tf32<<<dim3(DH/128, gy2), 256, SMEM_G>>>(xn, wf1, bf1, nullptr, h, MY, DH, D,
                                                  D, D, DH, 1,0,0,0,0,0, 1.0f, 1 | 4);
    gemm_tf32<<<dim3(D/128, gy2), 256, SMEM_G>>>(h, wf2, bf2, y, y, MY, D, DH,
                                                 DH, DH, D, 1,0,0,0,0,0, 1.0f, 2);
}